// round 1
// baseline (speedup 1.0000x reference)
#include <cuda_runtime.h>
#include <math.h>

#define BB 4
#define TT 4096
#define CC 1024
#define HH 128

// Scratch for Q,K,V projections (allocation-free: __device__ globals)
__device__ float g_Q[BB * TT * HH];
__device__ float g_K[BB * TT * HH];
__device__ float g_V[BB * TT * HH];

// ---------------------------------------------------------------------------
// Projection GEMM: out[m,h] = sum_k X[m,k] * W[k,h];  M=16384, K=1024, N=128
// CTA tile: 64 rows x 128 cols, 256 threads, per-thread 4x8 register tile.
// ---------------------------------------------------------------------------
#define PBM 64
#define PBK 32

__global__ __launch_bounds__(256, 2)
void proj_kernel(const float* __restrict__ X, const float* __restrict__ W,
                 float* __restrict__ out) {
    __shared__ __align__(16) float Xs[PBM][PBK + 4];   // stride 36 (16B-friendly, no conflicts)
    __shared__ __align__(16) float Ws[PBK][HH + 4];    // stride 132

    const int m0  = blockIdx.x * PBM;
    const int tid = threadIdx.x;
    const int rg  = tid >> 4;   // 0..15 : row group (4 rows)
    const int hg  = tid & 15;   // 0..15 : col group (8 cols)

    float acc[4][8];
#pragma unroll
    for (int r = 0; r < 4; r++)
#pragma unroll
        for (int i = 0; i < 8; i++) acc[r][i] = 0.f;

    for (int k0 = 0; k0 < CC; k0 += PBK) {
        // Load X tile 64x32 (512 float4, 2 per thread, coalesced)
#pragma unroll
        for (int l = 0; l < 2; l++) {
            int idx = tid + l * 256;          // 0..511
            int r   = idx >> 3;               // 8 float4 per row
            int cv  = (idx & 7) << 2;
            float4 v = *(const float4*)&X[(m0 + r) * CC + k0 + cv];
            Xs[r][cv + 0] = v.x; Xs[r][cv + 1] = v.y;
            Xs[r][cv + 2] = v.z; Xs[r][cv + 3] = v.w;
        }
        // Load W tile 32x128 (1024 float4, 4 per thread, coalesced)
#pragma unroll
        for (int l = 0; l < 4; l++) {
            int idx = tid + l * 256;          // 0..1023
            int r   = idx >> 5;               // 32 float4 per row
            int cv  = (idx & 31) << 2;
            float4 v = *(const float4*)&W[(k0 + r) * HH + cv];
            *(float4*)&Ws[r][cv] = v;
        }
        __syncthreads();

#pragma unroll 8
        for (int kk = 0; kk < PBK; kk++) {
            float x[4];
#pragma unroll
            for (int r = 0; r < 4; r++) x[r] = Xs[rg * 4 + r][kk];
            float4 w0 = *(float4*)&Ws[kk][hg * 8];
            float4 w1 = *(float4*)&Ws[kk][hg * 8 + 4];
#pragma unroll
            for (int r = 0; r < 4; r++) {
                acc[r][0] += x[r] * w0.x; acc[r][1] += x[r] * w0.y;
                acc[r][2] += x[r] * w0.z; acc[r][3] += x[r] * w0.w;
                acc[r][4] += x[r] * w1.x; acc[r][5] += x[r] * w1.y;
                acc[r][6] += x[r] * w1.z; acc[r][7] += x[r] * w1.w;
            }
        }
        __syncthreads();
    }

#pragma unroll
    for (int r = 0; r < 4; r++) {
        int row = m0 + rg * 4 + r;
        float4 o0 = make_float4(acc[r][0], acc[r][1], acc[r][2], acc[r][3]);
        float4 o1 = make_float4(acc[r][4], acc[r][5], acc[r][6], acc[r][7]);
        *(float4*)&out[row * HH + hg * 8]     = o0;
        *(float4*)&out[row * HH + hg * 8 + 4] = o1;
    }
}

// ---------------------------------------------------------------------------
// Flash attention (causal, fp32, online softmax)
// CTA: 64 queries x H=128, key tiles of 64. 256 threads.
//   Score phase : thread (rg,cg) computes 4 rows x 4 keys
//   PV phase    : thread (rg,cg) owns 4 rows x 8 head dims
// SMEM: Qs/Ks/Vs [64][132], P [64][68]  => 118784 bytes dynamic
// ---------------------------------------------------------------------------
#define AM 64
#define AN 64
#define QSTRIDE 132
#define PSTRIDE 68

__global__ __launch_bounds__(256)
void attn_kernel(const float* __restrict__ Q, const float* __restrict__ K,
                 const float* __restrict__ V, float* __restrict__ out) {
    extern __shared__ __align__(16) float smem[];
    float (*Qs)[QSTRIDE] = (float(*)[QSTRIDE])smem;
    float (*Ks)[QSTRIDE] = (float(*)[QSTRIDE])(smem + AM * QSTRIDE);
    float (*Vs)[QSTRIDE] = (float(*)[QSTRIDE])(smem + 2 * AM * QSTRIDE);
    float (*P)[PSTRIDE]  = (float(*)[PSTRIDE])(smem + 3 * AM * QSTRIDE);

    const int tid = threadIdx.x;
    const int rg  = tid >> 4;   // 0..15
    const int cg  = tid & 15;   // 0..15

    // Heavy q-tiles first for wave balance
    const int b  = blockIdx.x & 3;
    const int qt = (TT / AM) - 1 - (blockIdx.x >> 2);
    const int q0 = qt * AM;

    const float scale = 0.08838834764831845f;  // 1/sqrt(128)

    // Load + pre-scale Q tile (2048 float4, 8 per thread)
#pragma unroll
    for (int l = 0; l < 8; l++) {
        int idx = tid + l * 256;
        int r   = idx >> 5;
        int cv  = (idx & 31) << 2;
        float4 v = *(const float4*)&Q[(b * TT + q0 + r) * HH + cv];
        Qs[r][cv + 0] = v.x * scale; Qs[r][cv + 1] = v.y * scale;
        Qs[r][cv + 2] = v.z * scale; Qs[r][cv + 3] = v.w * scale;
    }

    float m[4], l_[4], acc[4][8];
#pragma unroll
    for (int r = 0; r < 4; r++) {
        m[r] = -1e30f; l_[r] = 0.f;
#pragma unroll
        for (int i = 0; i < 8; i++) acc[r][i] = 0.f;
    }

    for (int kt = 0; kt <= qt; kt++) {
        const int k0 = kt * AN;
        __syncthreads();  // protect Ks/Vs/P reuse from previous iteration

        // Load K and V tiles (2048 float4 each, 8+8 per thread)
#pragma unroll
        for (int l = 0; l < 8; l++) {
            int idx = tid + l * 256;
            int r   = idx >> 5;
            int cv  = (idx & 31) << 2;
            *(float4*)&Ks[r][cv] = *(const float4*)&K[(b * TT + k0 + r) * HH + cv];
            *(float4*)&Vs[r][cv] = *(const float4*)&V[(b * TT + k0 + r) * HH + cv];
        }
        __syncthreads();

        // ---- Score phase: s[4 rows][4 keys] ----
        float s[4][4];
#pragma unroll
        for (int r = 0; r < 4; r++)
#pragma unroll
            for (int j = 0; j < 4; j++) s[r][j] = 0.f;

#pragma unroll 4
        for (int h4 = 0; h4 < HH / 4; h4++) {
            float4 q[4], k[4];
#pragma unroll
            for (int r = 0; r < 4; r++) q[r] = *(float4*)&Qs[rg * 4 + r][h4 * 4];
#pragma unroll
            for (int j = 0; j < 4; j++) k[j] = *(float4*)&Ks[cg * 4 + j][h4 * 4];
#pragma unroll
            for (int r = 0; r < 4; r++)
#pragma unroll
                for (int j = 0; j < 4; j++)
                    s[r][j] += q[r].x * k[j].x + q[r].y * k[j].y +
                               q[r].z * k[j].z + q[r].w * k[j].w;
        }

        // Causal mask on diagonal tile
        if (kt == qt) {
#pragma unroll
            for (int r = 0; r < 4; r++) {
                int qg = q0 + rg * 4 + r;
#pragma unroll
                for (int j = 0; j < 4; j++) {
                    int jg = k0 + cg * 4 + j;
                    if (jg > qg) s[r][j] = -1e30f;
                }
            }
        }

        // ---- Online softmax (16-lane reductions over the cg dimension) ----
        float alpha[4];
#pragma unroll
        for (int r = 0; r < 4; r++) {
            float mx = fmaxf(fmaxf(s[r][0], s[r][1]), fmaxf(s[r][2], s[r][3]));
#pragma unroll
            for (int ofs = 1; ofs < 16; ofs <<= 1)
                mx = fmaxf(mx, __shfl_xor_sync(0xffffffffu, mx, ofs));
            float mnew = fmaxf(m[r], mx);
            alpha[r] = __expf(m[r] - mnew);
            float p0 = __expf(s[r][0] - mnew);
            float p1 = __expf(s[r][1] - mnew);
            float p2 = __expf(s[r][2] - mnew);
            float p3 = __expf(s[r][3] - mnew);
            *(float4*)&P[rg * 4 + r][cg * 4] = make_float4(p0, p1, p2, p3);
            float lsum = p0 + p1 + p2 + p3;
#pragma unroll
            for (int ofs = 1; ofs < 16; ofs <<= 1)
                lsum += __shfl_xor_sync(0xffffffffu, lsum, ofs);
            l_[r] = l_[r] * alpha[r] + lsum;
            m[r]  = mnew;
        }
        __syncthreads();  // P visible to all

        // ---- PV phase: acc[4 rows][8 dims] ----
#pragma unroll
        for (int r = 0; r < 4; r++)
#pragma unroll
            for (int i = 0; i < 8; i++) acc[r][i] *= alpha[r];

#pragma unroll 4
        for (int j4 = 0; j4 < AN / 4; j4++) {
            float pl[4][4];
#pragma unroll
            for (int r = 0; r < 4; r++) {
                float4 pv = *(float4*)&P[rg * 4 + r][j4 * 4];
                pl[r][0] = pv.x; pl[r][1] = pv.y; pl[r][2] = pv.z; pl[r][3] = pv.w;
            }
#pragma unroll
            for (int jj = 0; jj < 4; jj++) {
                float4 v0 = *(float4*)&Vs[j4 * 4 + jj][cg * 8];
                float4 v1 = *(float4*)&Vs[j4 * 4 + jj][cg * 8 + 4];
#pragma unroll
                for (int r = 0; r < 4; r++) {
                    float p = pl[r][jj];
                    acc[r][0] += p * v0.x; acc[r][1] += p * v0.y;
                    acc[r][2] += p * v0.z; acc[r][3] += p * v0.w;
                    acc[r][4] += p * v1.x; acc[r][5] += p * v1.y;
                    acc[r][6] += p * v1.z; acc[r][7] += p * v1.w;
                }
            }
        }
    }

    // ---- Epilogue: normalize and write ----
#pragma unroll
    for (int r = 0; r < 4; r++) {
        float inv = 1.0f / l_[r];
        int row = b * TT + q0 + rg * 4 + r;
        float4 o0 = make_float4(acc[r][0] * inv, acc[r][1] * inv,
                                acc[r][2] * inv, acc[r][3] * inv);
        float4 o1 = make_float4(acc[r][4] * inv, acc[r][5] * inv,
                                acc[r][6] * inv, acc[r][7] * inv);
        *(float4*)&out[row * HH + cg * 8]     = o0;
        *(float4*)&out[row * HH + cg * 8 + 4] = o1;
    }
}

// ---------------------------------------------------------------------------
extern "C" void kernel_launch(void* const* d_in, const int* in_sizes, int n_in,
                              void* d_out, int out_size) {
    const float* x  = (const float*)d_in[0];
    const float* Wq = (const float*)d_in[1];
    const float* Wk = (const float*)d_in[2];
    const float* Wv = (const float*)d_in[3];
    float* out = (float*)d_out;

    float *Qp, *Kp, *Vp;
    cudaGetSymbolAddress((void**)&Qp, g_Q);
    cudaGetSymbolAddress((void**)&Kp, g_K);
    cudaGetSymbolAddress((void**)&Vp, g_V);

    const int MBLK = (BB * TT) / PBM;  // 256
    proj_kernel<<<MBLK, 256>>>(x, Wq, Qp);
    proj_kernel<<<MBLK, 256>>>(x, Wk, Kp);
    proj_kernel<<<MBLK, 256>>>(x, Wv, Vp);

    const int ATT_SMEM = (3 * AM * QSTRIDE + AM * PSTRIDE) * (int)sizeof(float); // 118784
    cudaFuncSetAttribute(attn_kernel, cudaFuncAttributeMaxDynamicSharedMemorySize, ATT_SMEM);
    attn_kernel<<<BB * (TT / AM), 256, ATT_SMEM>>>(Qp, Kp, Vp, out);
}

// round 2
// speedup vs baseline: 2.9719x; 2.9719x over previous
#include <cuda_runtime.h>
#include <cuda_bf16.h>
#include <stdint.h>

#define BB 4
#define TT 4096
#define CC 1024
#define HH 128
#define MT (BB * TT)          // 16384 tokens total

// ---------------- global scratch (allocation-free) ----------------
__device__ __nv_bfloat16 g_xh[MT * CC];
__device__ __nv_bfloat16 g_xl[MT * CC];
__device__ __nv_bfloat16 g_Wth[3 * HH * CC];   // transposed weights [h][c]
__device__ __nv_bfloat16 g_Wtl[3 * HH * CC];
__device__ __nv_bfloat16 g_Qh[MT * HH], g_Ql[MT * HH];
__device__ __nv_bfloat16 g_Kh[MT * HH], g_Kl[MT * HH];
__device__ __nv_bfloat16 g_Vth[HH * MT], g_Vtl[HH * MT];   // V transposed [h][token]

// ---------------- helpers ----------------
__device__ __forceinline__ uint32_t bpack(__nv_bfloat16 a, __nv_bfloat16 b) {
    return (uint32_t)__bfloat16_as_ushort(a) | ((uint32_t)__bfloat16_as_ushort(b) << 16);
}
__device__ __forceinline__ void split1(float v, __nv_bfloat16& h, __nv_bfloat16& l) {
    h = __float2bfloat16(v);
    l = __float2bfloat16(v - __bfloat162float(h));
}
__device__ __forceinline__ void split_pack(float a, float b, uint32_t& hi, uint32_t& lo) {
    __nv_bfloat16 ah, al_, bh, bl_;
    split1(a, ah, al_); split1(b, bh, bl_);
    hi = bpack(ah, bh); lo = bpack(al_, bl_);
}

// fast exp for x <= 0 on FMA pipe (no MUFU). rel err ~2e-7.
__device__ __forceinline__ float fexp(float x) {
    float y = fmaxf(x * 1.4426950408889634f, -126.0f);
    float t = y + 12582912.0f;          // round-to-nearest-int trick
    float fi = t - 12582912.0f;
    float f  = y - fi;                  // [-0.5, 0.5]
    float z  = f * 0.6931471805599453f;
    float p = 1.3888888889e-3f;
    p = fmaf(p, z, 8.3333333333e-3f);
    p = fmaf(p, z, 4.1666666667e-2f);
    p = fmaf(p, z, 1.6666666667e-1f);
    p = fmaf(p, z, 0.5f);
    p = fmaf(p, z, 1.0f);
    p = fmaf(p, z, 1.0f);
    int e = __float_as_int(t) - 0x4B400000;        // integer part of y
    float sc = __int_as_float((e + 127) << 23);    // 2^e (e in [-126,0])
    return p * sc;
}

#define MMA(d, a, b0_, b1_) asm volatile( \
    "mma.sync.aligned.m16n8k16.row.col.f32.bf16.bf16.f32 " \
    "{%0,%1,%2,%3}, {%4,%5,%6,%7}, {%8,%9}, {%0,%1,%2,%3};\n" \
    : "+f"(d[0]), "+f"(d[1]), "+f"(d[2]), "+f"(d[3]) \
    : "r"(a[0]), "r"(a[1]), "r"(a[2]), "r"(a[3]), "r"(b0_), "r"(b1_))

// ---------------- conversion kernels ----------------
__global__ void conv_x(const float* __restrict__ x) {
    int i = blockIdx.x * blockDim.x + threadIdx.x;
    int stride = gridDim.x * blockDim.x;
    const int n4 = MT * CC / 4;
    for (; i < n4; i += stride) {
        float4 v = ((const float4*)x)[i];
        __nv_bfloat16 h0, l0, h1, l1, h2, l2, h3, l3;
        split1(v.x, h0, l0); split1(v.y, h1, l1);
        split1(v.z, h2, l2); split1(v.w, h3, l3);
        ushort4 hh = make_ushort4(__bfloat16_as_ushort(h0), __bfloat16_as_ushort(h1),
                                  __bfloat16_as_ushort(h2), __bfloat16_as_ushort(h3));
        ushort4 ll = make_ushort4(__bfloat16_as_ushort(l0), __bfloat16_as_ushort(l1),
                                  __bfloat16_as_ushort(l2), __bfloat16_as_ushort(l3));
        ((ushort4*)g_xh)[i] = hh;
        ((ushort4*)g_xl)[i] = ll;
    }
}

__global__ void conv_w(const float* __restrict__ Wq, const float* __restrict__ Wk,
                       const float* __restrict__ Wv) {
    int i = blockIdx.x * blockDim.x + threadIdx.x;
    if (i >= 3 * CC * HH) return;
    int w = i / (CC * HH);
    int r = i % (CC * HH);
    int c = r / HH, h = r % HH;
    const float* W = (w == 0) ? Wq : (w == 1) ? Wk : Wv;
    __nv_bfloat16 bh, bl;
    split1(W[c * HH + h], bh, bl);
    g_Wth[w * HH * CC + h * CC + c] = bh;
    g_Wtl[w * HH * CC + h * CC + c] = bl;
}

// ---------------- projection GEMM (bf16x3 mma) ----------------
// out[token][h] = sum_c x[token][c] * W[c][h];  CTA = 128 tokens x 128 h, 8 warps
#define SX 72     // smem stride for 64-wide tiles
#define SQ 136    // smem stride for 128-wide tiles

__global__ __launch_bounds__(256)
void proj_mma(int mode, float scale) {
    extern __shared__ __nv_bfloat16 sm[];
    __nv_bfloat16* Xh = sm;
    __nv_bfloat16* Xl = Xh + 128 * SX;
    __nv_bfloat16* Wh = Xl + 128 * SX;
    __nv_bfloat16* Wl = Wh + 128 * SX;

    const int tid = threadIdx.x;
    const int warp = tid >> 5, lane = tid & 31;
    const int gid = lane >> 2, tig = lane & 3;
    const int row0 = blockIdx.x * 128;
    const __nv_bfloat16* wbh = g_Wth + mode * HH * CC;
    const __nv_bfloat16* wbl = g_Wtl + mode * HH * CC;

    float acc[16][4];
#pragma unroll
    for (int n = 0; n < 16; n++)
#pragma unroll
        for (int j = 0; j < 4; j++) acc[n][j] = 0.f;

    for (int c0 = 0; c0 < CC; c0 += 64) {
        __syncthreads();
#pragma unroll
        for (int i = 0; i < 4; i++) {
            int idx = tid + i * 256;
            int r = idx >> 3, cc = (idx & 7) * 8;
            *(uint4*)&Xh[r * SX + cc] = *(const uint4*)&g_xh[(row0 + r) * CC + c0 + cc];
            *(uint4*)&Xl[r * SX + cc] = *(const uint4*)&g_xl[(row0 + r) * CC + c0 + cc];
            *(uint4*)&Wh[r * SX + cc] = *(const uint4*)&wbh[r * CC + c0 + cc];
            *(uint4*)&Wl[r * SX + cc] = *(const uint4*)&wbl[r * CC + c0 + cc];
        }
        __syncthreads();

        const int arow = warp * 16 + gid;
#pragma unroll
        for (int kt = 0; kt < 4; kt++) {
            const int kc = kt * 16 + tig * 2;
            uint32_t ah[4], al[4];
            ah[0] = *(uint32_t*)&Xh[arow * SX + kc];
            ah[1] = *(uint32_t*)&Xh[(arow + 8) * SX + kc];
            ah[2] = *(uint32_t*)&Xh[arow * SX + kc + 8];
            ah[3] = *(uint32_t*)&Xh[(arow + 8) * SX + kc + 8];
            al[0] = *(uint32_t*)&Xl[arow * SX + kc];
            al[1] = *(uint32_t*)&Xl[(arow + 8) * SX + kc];
            al[2] = *(uint32_t*)&Xl[arow * SX + kc + 8];
            al[3] = *(uint32_t*)&Xl[(arow + 8) * SX + kc + 8];
#pragma unroll
            for (int n = 0; n < 16; n++) {
                const int br = n * 8 + gid;
                uint32_t bh0 = *(uint32_t*)&Wh[br * SX + kc];
                uint32_t bh1 = *(uint32_t*)&Wh[br * SX + kc + 8];
                uint32_t bl0 = *(uint32_t*)&Wl[br * SX + kc];
                uint32_t bl1 = *(uint32_t*)&Wl[br * SX + kc + 8];
                MMA(acc[n], ah, bh0, bh1);
                MMA(acc[n], ah, bl0, bl1);
                MMA(acc[n], al, bh0, bh1);
            }
        }
    }

    // epilogue
    const int r0 = row0 + warp * 16 + gid;
    if (mode < 2) {
        __nv_bfloat16* oh = (mode == 0) ? g_Qh : g_Kh;
        __nv_bfloat16* ol = (mode == 0) ? g_Ql : g_Kl;
#pragma unroll
        for (int n = 0; n < 16; n++) {
            const int h = n * 8 + tig * 2;
            uint32_t hi, lo;
            split_pack(acc[n][0] * scale, acc[n][1] * scale, hi, lo);
            *(uint32_t*)&oh[r0 * HH + h] = hi;
            *(uint32_t*)&ol[r0 * HH + h] = lo;
            split_pack(acc[n][2] * scale, acc[n][3] * scale, hi, lo);
            *(uint32_t*)&oh[(r0 + 8) * HH + h] = hi;
            *(uint32_t*)&ol[(r0 + 8) * HH + h] = lo;
        }
    } else {  // V: write transposed [h][token]
#pragma unroll
        for (int n = 0; n < 16; n++) {
            const int h = n * 8 + tig * 2;
            __nv_bfloat16 bh, bl;
            split1(acc[n][0], bh, bl); g_Vth[h * MT + r0] = bh;       g_Vtl[h * MT + r0] = bl;
            split1(acc[n][1], bh, bl); g_Vth[(h + 1) * MT + r0] = bh; g_Vtl[(h + 1) * MT + r0] = bl;
            split1(acc[n][2], bh, bl); g_Vth[h * MT + r0 + 8] = bh;   g_Vtl[h * MT + r0 + 8] = bl;
            split1(acc[n][3], bh, bl); g_Vth[(h + 1) * MT + r0 + 8] = bh; g_Vtl[(h + 1) * MT + r0 + 8] = bl;
        }
    }
}

// ---------------- flash attention (bf16x3 mma, causal, online softmax) ----------------
// CTA: 64 queries (4 warps x 16 rows), key tiles of 64, P kept in registers.
__global__ __launch_bounds__(128, 2)
void attn_mma(float* __restrict__ out) {
    extern __shared__ __nv_bfloat16 sm[];
    __nv_bfloat16* Qh = sm;                       // [64][136]
    __nv_bfloat16* Ql = Qh + 64 * SQ;
    __nv_bfloat16* Kh = Ql + 64 * SQ;             // [64][136]
    __nv_bfloat16* Kl = Kh + 64 * SQ;
    __nv_bfloat16* Vh = Kl + 64 * SQ;             // [128][72] (transposed: [h][key])
    __nv_bfloat16* Vl = Vh + 128 * SX;

    const int tid = threadIdx.x;
    const int warp = tid >> 5, lane = tid & 31;
    const int gid = lane >> 2, tig = lane & 3;

    const int bi = blockIdx.x;
    const int b = bi & 3;
    const int qt = (TT / 64) - 1 - (bi >> 2);     // heavy tiles first
    const int qbase = qt * 64;
    const int tb = b * TT;

    // stage Q
#pragma unroll
    for (int i = 0; i < 8; i++) {
        int idx = tid + i * 128;
        int r = idx >> 4, cc = (idx & 15) * 8;
        *(uint4*)&Qh[r * SQ + cc] = *(const uint4*)&g_Qh[(tb + qbase + r) * HH + cc];
        *(uint4*)&Ql[r * SQ + cc] = *(const uint4*)&g_Ql[(tb + qbase + r) * HH + cc];
    }

    float O[16][4];
#pragma unroll
    for (int n = 0; n < 16; n++)
#pragma unroll
        for (int j = 0; j < 4; j++) O[n][j] = 0.f;
    float m0 = -1e30f, m1 = -1e30f, l0 = 0.f, l1 = 0.f;
    const int arow = warp * 16 + gid;

    for (int kt = 0; kt <= qt; kt++) {
        const int k0 = kt * 64;
        __syncthreads();
#pragma unroll
        for (int i = 0; i < 8; i++) {
            int idx = tid + i * 128;
            int r = idx >> 4, cc = (idx & 15) * 8;
            *(uint4*)&Kh[r * SQ + cc] = *(const uint4*)&g_Kh[(tb + k0 + r) * HH + cc];
            *(uint4*)&Kl[r * SQ + cc] = *(const uint4*)&g_Kl[(tb + k0 + r) * HH + cc];
            int vr = idx >> 3, vc = (idx & 7) * 8;
            *(uint4*)&Vh[vr * SX + vc] = *(const uint4*)&g_Vth[vr * MT + tb + k0 + vc];
            *(uint4*)&Vl[vr * SX + vc] = *(const uint4*)&g_Vtl[vr * MT + tb + k0 + vc];
        }
        __syncthreads();

        // ---- S = Q K^T (x3) ----
        float s[8][4];
#pragma unroll
        for (int n = 0; n < 8; n++)
#pragma unroll
            for (int j = 0; j < 4; j++) s[n][j] = 0.f;

#pragma unroll
        for (int kk = 0; kk < 8; kk++) {
            const int kc = kk * 16 + tig * 2;
            uint32_t ah[4], al[4];
            ah[0] = *(uint32_t*)&Qh[arow * SQ + kc];
            ah[1] = *(uint32_t*)&Qh[(arow + 8) * SQ + kc];
            ah[2] = *(uint32_t*)&Qh[arow * SQ + kc + 8];
            ah[3] = *(uint32_t*)&Qh[(arow + 8) * SQ + kc + 8];
            al[0] = *(uint32_t*)&Ql[arow * SQ + kc];
            al[1] = *(uint32_t*)&Ql[(arow + 8) * SQ + kc];
            al[2] = *(uint32_t*)&Ql[arow * SQ + kc + 8];
            al[3] = *(uint32_t*)&Ql[(arow + 8) * SQ + kc + 8];
#pragma unroll
            for (int n = 0; n < 8; n++) {
                const int br = n * 8 + gid;
                uint32_t bh0 = *(uint32_t*)&Kh[br * SQ + kc];
                uint32_t bh1 = *(uint32_t*)&Kh[br * SQ + kc + 8];
                uint32_t bl0 = *(uint32_t*)&Kl[br * SQ + kc];
                uint32_t bl1 = *(uint32_t*)&Kl[br * SQ + kc + 8];
                MMA(s[n], ah, bh0, bh1);
                MMA(s[n], ah, bl0, bl1);
                MMA(s[n], al, bh0, bh1);
            }
        }

        // causal mask (only diagonal tile)
        if (kt == qt) {
#pragma unroll
            for (int n = 0; n < 8; n++) {
                const int keyb = n * 8 + tig * 2;
                const int rl0 = warp * 16 + gid, rl1 = rl0 + 8;
                if (keyb     > rl0) s[n][0] = -1e30f;
                if (keyb + 1 > rl0) s[n][1] = -1e30f;
                if (keyb     > rl1) s[n][2] = -1e30f;
                if (keyb + 1 > rl1) s[n][3] = -1e30f;
            }
        }

        // ---- online softmax ----
        float rmax0 = -1e30f, rmax1 = -1e30f;
#pragma unroll
        for (int n = 0; n < 8; n++) {
            rmax0 = fmaxf(rmax0, fmaxf(s[n][0], s[n][1]));
            rmax1 = fmaxf(rmax1, fmaxf(s[n][2], s[n][3]));
        }
        rmax0 = fmaxf(rmax0, __shfl_xor_sync(0xffffffffu, rmax0, 1));
        rmax0 = fmaxf(rmax0, __shfl_xor_sync(0xffffffffu, rmax0, 2));
        rmax1 = fmaxf(rmax1, __shfl_xor_sync(0xffffffffu, rmax1, 1));
        rmax1 = fmaxf(rmax1, __shfl_xor_sync(0xffffffffu, rmax1, 2));

        const float mn0 = fmaxf(m0, rmax0), mn1 = fmaxf(m1, rmax1);
        const float al0 = fexp(m0 - mn0), al1 = fexp(m1 - mn1);
        m0 = mn0; m1 = mn1;

        float rs0 = 0.f, rs1 = 0.f;
        uint32_t pah[4][4], pal[4][4];
#pragma unroll
        for (int n = 0; n < 8; n++) {
            float p0 = fexp(s[n][0] - mn0);
            float p1 = fexp(s[n][1] - mn0);
            float p2 = fexp(s[n][2] - mn1);
            float p3 = fexp(s[n][3] - mn1);
            rs0 += p0 + p1; rs1 += p2 + p3;
            const int kti = n >> 1, base = (n & 1) * 2;
            split_pack(p0, p1, pah[kti][base], pal[kti][base]);
            split_pack(p2, p3, pah[kti][base + 1], pal[kti][base + 1]);
        }
        rs0 += __shfl_xor_sync(0xffffffffu, rs0, 1);
        rs0 += __shfl_xor_sync(0xffffffffu, rs0, 2);
        rs1 += __shfl_xor_sync(0xffffffffu, rs1, 1);
        rs1 += __shfl_xor_sync(0xffffffffu, rs1, 2);
        l0 = l0 * al0 + rs0;
        l1 = l1 * al1 + rs1;

#pragma unroll
        for (int n = 0; n < 16; n++) {
            O[n][0] *= al0; O[n][1] *= al0;
            O[n][2] *= al1; O[n][3] *= al1;
        }

        // ---- O += P V (x3) ----
#pragma unroll
        for (int nt = 0; nt < 16; nt++) {
            const int vb = nt * 8 + gid;
#pragma unroll
            for (int kk = 0; kk < 4; kk++) {
                const int kc = kk * 16 + tig * 2;
                uint32_t bh0 = *(uint32_t*)&Vh[vb * SX + kc];
                uint32_t bh1 = *(uint32_t*)&Vh[vb * SX + kc + 8];
                uint32_t bl0 = *(uint32_t*)&Vl[vb * SX + kc];
                uint32_t bl1 = *(uint32_t*)&Vl[vb * SX + kc + 8];
                MMA(O[nt], pah[kk], bh0, bh1);
                MMA(O[nt], pah[kk], bl0, bl1);
                MMA(O[nt], pal[kk], bh0, bh1);
            }
        }
    }

    // epilogue
    const float i0 = 1.f / l0, i1 = 1.f / l1;
    const int r0g = tb + qbase + warp * 16 + gid;
#pragma unroll
    for (int nt = 0; nt < 16; nt++) {
        const int h = nt * 8 + tig * 2;
        float2 v0 = make_float2(O[nt][0] * i0, O[nt][1] * i0);
        float2 v1 = make_float2(O[nt][2] * i1, O[nt][3] * i1);
        *(float2*)&out[r0g * HH + h] = v0;
        *(float2*)&out[(r0g + 8) * HH + h] = v1;
    }
}

// ---------------- launch ----------------
extern "C" void kernel_launch(void* const* d_in, const int* in_sizes, int n_in,
                              void* d_out, int out_size) {
    const float* x  = (const float*)d_in[0];
    const float* Wq = (const float*)d_in[1];
    const float* Wk = (const float*)d_in[2];
    const float* Wv = (const float*)d_in[3];
    float* out = (float*)d_out;

    conv_x<<<4096, 256>>>(x);
    conv_w<<<(3 * CC * HH + 255) / 256, 256>>>(Wq, Wk, Wv);

    const int PJ_SMEM = 4 * 128 * SX * (int)sizeof(__nv_bfloat16);   // 73728
    cudaFuncSetAttribute(proj_mma, cudaFuncAttributeMaxDynamicSharedMemorySize, PJ_SMEM);
    const float scale = 0.08838834764831845f;   // 1/sqrt(128), folded into Q
    proj_mma<<<MT / 128, 256, PJ_SMEM>>>(0, scale);
    proj_mma<<<MT / 128, 256, PJ_SMEM>>>(1, 1.0f);
    proj_mma<<<MT / 128, 256, PJ_SMEM>>>(2, 1.0f);

    const int AT_SMEM = (4 * 64 * SQ + 2 * 128 * SX) * (int)sizeof(__nv_bfloat16); // 106496
    cudaFuncSetAttribute(attn_mma, cudaFuncAttributeMaxDynamicSharedMemorySize, AT_SMEM);
    attn_mma<<<BB * (TT / 64), 128, AT_SMEM>>>(out);
}

// round 3
// speedup vs baseline: 4.1954x; 1.4117x over previous
#include <cuda_runtime.h>
#include <cuda_bf16.h>
#include <stdint.h>

#define BB 4
#define TT 4096
#define CC 1024
#define HH 128
#define MT (BB * TT)

// ---------------- global scratch (allocation-free) ----------------
__device__ __nv_bfloat16 g_Wth[3 * HH * CC];   // transposed weights [mode][h][c], hi
__device__ __nv_bfloat16 g_Wtl[3 * HH * CC];   // lo
__device__ __nv_bfloat16 g_Qh[MT * HH], g_Ql[MT * HH];
__device__ __nv_bfloat16 g_Kh[MT * HH], g_Kl[MT * HH];
__device__ __nv_bfloat16 g_Vth[HH * MT], g_Vtl[HH * MT];   // V transposed [h][token]
__device__ float  g_Op[2 * MT * HH];           // split-K partial O (unnormalized)
__device__ float2 g_ML[2 * MT];                // split-K partial (m, l)

// ---------------- helpers ----------------
__device__ __forceinline__ uint32_t bpack(__nv_bfloat16 a, __nv_bfloat16 b) {
    return (uint32_t)__bfloat16_as_ushort(a) | ((uint32_t)__bfloat16_as_ushort(b) << 16);
}
__device__ __forceinline__ void split1(float v, __nv_bfloat16& h, __nv_bfloat16& l) {
    h = __float2bfloat16(v);
    l = __float2bfloat16(v - __bfloat162float(h));
}
__device__ __forceinline__ void split_pack(float a, float b, uint32_t& hi, uint32_t& lo) {
    __nv_bfloat16 ah, al_, bh, bl_;
    split1(a, ah, al_); split1(b, bh, bl_);
    hi = bpack(ah, bh); lo = bpack(al_, bl_);
}
__device__ __forceinline__ uint32_t saddr(const void* p) {
    return (uint32_t)__cvta_generic_to_shared(p);
}
// fast exp on the FMA pipe (x <= ~0). rel err ~2e-7.
__device__ __forceinline__ float fexp(float x) {
    float y = fmaxf(x * 1.4426950408889634f, -126.0f);
    float t = y + 12582912.0f;
    float fi = t - 12582912.0f;
    float z  = (y - fi) * 0.6931471805599453f;
    float p = 1.3888888889e-3f;
    p = fmaf(p, z, 8.3333333333e-3f);
    p = fmaf(p, z, 4.1666666667e-2f);
    p = fmaf(p, z, 1.6666666667e-1f);
    p = fmaf(p, z, 0.5f);
    p = fmaf(p, z, 1.0f);
    p = fmaf(p, z, 1.0f);
    int e = __float_as_int(t) - 0x4B400000;
    float sc = __int_as_float((e + 127) << 23);
    return p * sc;
}

#define MMA(d, a, b0_, b1_) asm volatile( \
    "mma.sync.aligned.m16n8k16.row.col.f32.bf16.bf16.f32 " \
    "{%0,%1,%2,%3}, {%4,%5,%6,%7}, {%8,%9}, {%0,%1,%2,%3};\n" \
    : "+f"(d[0]), "+f"(d[1]), "+f"(d[2]), "+f"(d[3]) \
    : "r"(a[0]), "r"(a[1]), "r"(a[2]), "r"(a[3]), "r"(b0_), "r"(b1_))

#define LDSM4(r, a) asm volatile( \
    "ldmatrix.sync.aligned.m8n8.x4.shared.b16 {%0,%1,%2,%3}, [%4];" \
    : "=r"((r)[0]), "=r"((r)[1]), "=r"((r)[2]), "=r"((r)[3]) : "r"(a))

// ---------------- weight conversion ----------------
__global__ void conv_w(const float* __restrict__ Wq, const float* __restrict__ Wk,
                       const float* __restrict__ Wv) {
    int i = blockIdx.x * blockDim.x + threadIdx.x;
    if (i >= 3 * CC * HH) return;
    int w = i / (CC * HH);
    int r = i % (CC * HH);
    int c = r / HH, h = r % HH;
    const float* W = (w == 0) ? Wq : (w == 1) ? Wk : Wv;
    __nv_bfloat16 bh, bl;
    split1(W[c * HH + h], bh, bl);
    g_Wth[w * HH * CC + h * CC + c] = bh;
    g_Wtl[w * HH * CC + h * CC + c] = bl;
}

// ---------------- fused projection GEMM (bf16x3, ldmatrix, dbl-buffered) ----
#define SX 72     // stride for 64-wide bf16 tiles (36 words; 36 mod 32 = 4 -> LDSM conflict-free)
#define SQ 136    // stride for 128-wide bf16 tiles (68 words; 68 mod 32 = 4)

#define PJ_PREFETCH(C0) do { \
    _Pragma("unroll") \
    for (int i_ = 0; i_ < 8; i_++) { \
        int idx_ = tid + i_ * 256; int r_ = idx_ >> 4, c4_ = (idx_ & 15) * 4; \
        xf[i_] = *(const float4*)&X[(size_t)(row0 + r_) * CC + (C0) + c4_]; \
    } \
    _Pragma("unroll") \
    for (int i_ = 0; i_ < 4; i_++) { \
        int idx_ = tid + i_ * 256; int r_ = idx_ >> 3, c8_ = (idx_ & 7) * 8; \
        wrh[i_] = *(const uint4*)&wbh[(size_t)r_ * CC + (C0) + c8_]; \
        wrl[i_] = *(const uint4*)&wbl[(size_t)r_ * CC + (C0) + c8_]; \
    } \
} while (0)

__global__ __launch_bounds__(256, 1)
void proj_mma(const float* __restrict__ X, float qscale) {
    extern __shared__ __nv_bfloat16 sm[];
    __nv_bfloat16* Xh = sm;                 // [128][SX]
    __nv_bfloat16* Xl = Xh + 128 * SX;
    __nv_bfloat16* Wh = Xl + 128 * SX;      // [128 h][SX]
    __nv_bfloat16* Wl = Wh + 128 * SX;

    const int tid = threadIdx.x, warp = tid >> 5, lane = tid & 31;
    const int gid = lane >> 2, tig = lane & 3;
    const int mode = blockIdx.y;
    const int row0 = blockIdx.x * 128;
    const __nv_bfloat16* wbh = g_Wth + (size_t)mode * HH * CC;
    const __nv_bfloat16* wbl = g_Wtl + (size_t)mode * HH * CC;

    float acc[16][4];
#pragma unroll
    for (int n = 0; n < 16; n++)
#pragma unroll
        for (int j = 0; j < 4; j++) acc[n][j] = 0.f;

    float4 xf[8]; uint4 wrh[4], wrl[4];
    PJ_PREFETCH(0);

    const int rr  = (lane & 7) + ((lane >> 3) & 1) * 8;   // ldmatrix lane row
    const int cc8 = (lane >> 4) * 8;                      // ldmatrix lane col

    for (int c0 = 0; c0 < CC; c0 += 64) {
        __syncthreads();
        // store staged tile (convert X fp32 -> bf16 hi/lo)
#pragma unroll
        for (int i = 0; i < 8; i++) {
            int idx = tid + i * 256; int r = idx >> 4, c4 = (idx & 15) * 4;
            float4 v = xf[i];
            __nv_bfloat16 h0, l0, h1, l1, h2, l2, h3, l3;
            split1(v.x, h0, l0); split1(v.y, h1, l1);
            split1(v.z, h2, l2); split1(v.w, h3, l3);
            *(uint32_t*)&Xh[r * SX + c4]     = bpack(h0, h1);
            *(uint32_t*)&Xh[r * SX + c4 + 2] = bpack(h2, h3);
            *(uint32_t*)&Xl[r * SX + c4]     = bpack(l0, l1);
            *(uint32_t*)&Xl[r * SX + c4 + 2] = bpack(l2, l3);
        }
#pragma unroll
        for (int i = 0; i < 4; i++) {
            int idx = tid + i * 256; int r = idx >> 3, c8 = (idx & 7) * 8;
            *(uint4*)&Wh[r * SX + c8] = wrh[i];
            *(uint4*)&Wl[r * SX + c8] = wrl[i];
        }
        __syncthreads();
        if (c0 + 64 < CC) { PJ_PREFETCH(c0 + 64); }   // overlap next loads with MMA

#pragma unroll
        for (int kt = 0; kt < 4; kt++) {
            const int kc = kt * 16;
            uint32_t ah[4], al[4];
            LDSM4(ah, saddr(&Xh[(warp * 16 + rr) * SX + kc + cc8]));
            LDSM4(al, saddr(&Xl[(warp * 16 + rr) * SX + kc + cc8]));
#pragma unroll
            for (int p = 0; p < 8; p++) {
                uint32_t bh[4], bl[4];
                LDSM4(bh, saddr(&Wh[(p * 16 + rr) * SX + kc + cc8]));
                LDSM4(bl, saddr(&Wl[(p * 16 + rr) * SX + kc + cc8]));
                MMA(acc[2 * p],     ah, bh[0], bh[2]);
                MMA(acc[2 * p],     ah, bl[0], bl[2]);
                MMA(acc[2 * p],     al, bh[0], bh[2]);
                MMA(acc[2 * p + 1], ah, bh[1], bh[3]);
                MMA(acc[2 * p + 1], ah, bl[1], bl[3]);
                MMA(acc[2 * p + 1], al, bh[1], bh[3]);
            }
        }
    }

    const float scale = (mode == 0) ? qscale : 1.0f;
    const int r0 = row0 + warp * 16 + gid;
    if (mode < 2) {
        __nv_bfloat16* oh = (mode == 0) ? g_Qh : g_Kh;
        __nv_bfloat16* ol = (mode == 0) ? g_Ql : g_Kl;
#pragma unroll
        for (int n = 0; n < 16; n++) {
            const int h = n * 8 + tig * 2;
            uint32_t hi, lo;
            split_pack(acc[n][0] * scale, acc[n][1] * scale, hi, lo);
            *(uint32_t*)&oh[(size_t)r0 * HH + h] = hi;
            *(uint32_t*)&ol[(size_t)r0 * HH + h] = lo;
            split_pack(acc[n][2] * scale, acc[n][3] * scale, hi, lo);
            *(uint32_t*)&oh[(size_t)(r0 + 8) * HH + h] = hi;
            *(uint32_t*)&ol[(size_t)(r0 + 8) * HH + h] = lo;
        }
    } else {  // V transposed [h][token]
#pragma unroll
        for (int n = 0; n < 16; n++) {
            const int h = n * 8 + tig * 2;
            __nv_bfloat16 bh, bl;
            split1(acc[n][0], bh, bl); g_Vth[(size_t)h * MT + r0] = bh;           g_Vtl[(size_t)h * MT + r0] = bl;
            split1(acc[n][1], bh, bl); g_Vth[(size_t)(h + 1) * MT + r0] = bh;     g_Vtl[(size_t)(h + 1) * MT + r0] = bl;
            split1(acc[n][2], bh, bl); g_Vth[(size_t)h * MT + r0 + 8] = bh;       g_Vtl[(size_t)h * MT + r0 + 8] = bl;
            split1(acc[n][3], bh, bl); g_Vth[(size_t)(h + 1) * MT + r0 + 8] = bh; g_Vtl[(size_t)(h + 1) * MT + r0 + 8] = bl;
        }
    }
}

// ---------------- flash attention: BM=128, BN=64, split-K=2 ----------------
#define AT_PREFETCH(KT) do { \
    const int k0_ = (KT) * 64; \
    _Pragma("unroll") \
    for (int i_ = 0; i_ < 4; i_++) { \
        int idx_ = tid + i_ * 256; \
        int r_ = idx_ >> 4, c_ = (idx_ & 15) * 8; \
        kh[i_] = *(const uint4*)&g_Kh[(size_t)(tb + k0_ + r_) * HH + c_]; \
        kl[i_] = *(const uint4*)&g_Kl[(size_t)(tb + k0_ + r_) * HH + c_]; \
        int vr_ = idx_ >> 3, vc_ = (idx_ & 7) * 8; \
        vh[i_] = *(const uint4*)&g_Vth[(size_t)vr_ * MT + tb + k0_ + vc_]; \
        vl[i_] = *(const uint4*)&g_Vtl[(size_t)vr_ * MT + tb + k0_ + vc_]; \
    } \
} while (0)

__global__ __launch_bounds__(256, 1)
void attn_mma() {
    extern __shared__ __nv_bfloat16 sm[];
    __nv_bfloat16* Qh = sm;                  // [128][SQ]
    __nv_bfloat16* Ql = Qh + 128 * SQ;
    __nv_bfloat16* Kh = Ql + 128 * SQ;       // [64][SQ]
    __nv_bfloat16* Kl = Kh + 64 * SQ;
    __nv_bfloat16* Vh = Kl + 64 * SQ;        // [128 h][SX] (key-contiguous)
    __nv_bfloat16* Vl = Vh + 128 * SX;

    const int tid = threadIdx.x, warp = tid >> 5, lane = tid & 31;
    const int gid = lane >> 2, tig = lane & 3;
    const int bx = blockIdx.x;
    const int qi    = 31 - (bx >> 3);        // heavy q-tiles first
    const int b     = (bx >> 1) & 3;
    const int split = bx & 1;
    const int qbase = qi * 128, tb = b * TT;
    const int kt0 = split ? (qi + 1) : 0;
    const int kt1 = split ? (2 * qi + 2) : (qi + 1);

    // stage Q (128 x 128 hi/lo)
#pragma unroll
    for (int i = 0; i < 8; i++) {
        int idx = tid + i * 256; int r = idx >> 4, c = (idx & 15) * 8;
        *(uint4*)&Qh[r * SQ + c] = *(const uint4*)&g_Qh[(size_t)(tb + qbase + r) * HH + c];
        *(uint4*)&Ql[r * SQ + c] = *(const uint4*)&g_Ql[(size_t)(tb + qbase + r) * HH + c];
    }

    float O[16][4];
#pragma unroll
    for (int n = 0; n < 16; n++)
#pragma unroll
        for (int j = 0; j < 4; j++) O[n][j] = 0.f;
    float m0 = -1e30f, m1 = -1e30f, l0 = 0.f, l1 = 0.f;

    const int rr  = (lane & 7) + ((lane >> 3) & 1) * 8;
    const int cc8 = (lane >> 4) * 8;

    uint4 kh[4], kl[4], vh[4], vl[4];
    AT_PREFETCH(kt0);

    for (int kt = kt0; kt < kt1; kt++) {
        __syncthreads();
#pragma unroll
        for (int i = 0; i < 4; i++) {
            int idx = tid + i * 256;
            int r = idx >> 4, c = (idx & 15) * 8;
            *(uint4*)&Kh[r * SQ + c] = kh[i];
            *(uint4*)&Kl[r * SQ + c] = kl[i];
            int vr = idx >> 3, vc = (idx & 7) * 8;
            *(uint4*)&Vh[vr * SX + vc] = vh[i];
            *(uint4*)&Vl[vr * SX + vc] = vl[i];
        }
        __syncthreads();
        if (kt + 1 < kt1) { AT_PREFETCH(kt + 1); }
        const int k0 = kt * 64;

        // ---- S = Q K^T (x3) ----
        float s[8][4];
#pragma unroll
        for (int n = 0; n < 8; n++)
#pragma unroll
            for (int j = 0; j < 4; j++) s[n][j] = 0.f;

#pragma unroll
        for (int kk = 0; kk < 8; kk++) {
            const int kc = kk * 16;
            uint32_t ah[4], al[4];
            LDSM4(ah, saddr(&Qh[(warp * 16 + rr) * SQ + kc + cc8]));
            LDSM4(al, saddr(&Ql[(warp * 16 + rr) * SQ + kc + cc8]));
#pragma unroll
            for (int p = 0; p < 4; p++) {
                uint32_t bh[4], bl[4];
                LDSM4(bh, saddr(&Kh[(p * 16 + rr) * SQ + kc + cc8]));
                LDSM4(bl, saddr(&Kl[(p * 16 + rr) * SQ + kc + cc8]));
                MMA(s[2 * p],     ah, bh[0], bh[2]);
                MMA(s[2 * p],     ah, bl[0], bl[2]);
                MMA(s[2 * p],     al, bh[0], bh[2]);
                MMA(s[2 * p + 1], ah, bh[1], bh[3]);
                MMA(s[2 * p + 1], ah, bl[1], bl[3]);
                MMA(s[2 * p + 1], al, bh[1], bh[3]);
            }
        }

        // ---- causal mask (only tiles overlapping the diagonal) ----
        if (kt >= 2 * qi) {
            const int row0g = qbase + warp * 16 + gid;
#pragma unroll
            for (int n = 0; n < 8; n++) {
                const int keyg = k0 + n * 8 + tig * 2;
                if (keyg     > row0g)     s[n][0] = -3e30f;
                if (keyg + 1 > row0g)     s[n][1] = -3e30f;
                if (keyg     > row0g + 8) s[n][2] = -3e30f;
                if (keyg + 1 > row0g + 8) s[n][3] = -3e30f;
            }
        }

        // ---- online softmax ----
        float rmax0 = -3e30f, rmax1 = -3e30f;
#pragma unroll
        for (int n = 0; n < 8; n++) {
            rmax0 = fmaxf(rmax0, fmaxf(s[n][0], s[n][1]));
            rmax1 = fmaxf(rmax1, fmaxf(s[n][2], s[n][3]));
        }
        rmax0 = fmaxf(rmax0, __shfl_xor_sync(0xffffffffu, rmax0, 1));
        rmax0 = fmaxf(rmax0, __shfl_xor_sync(0xffffffffu, rmax0, 2));
        rmax1 = fmaxf(rmax1, __shfl_xor_sync(0xffffffffu, rmax1, 1));
        rmax1 = fmaxf(rmax1, __shfl_xor_sync(0xffffffffu, rmax1, 2));

        const float mn0 = fmaxf(m0, rmax0), mn1 = fmaxf(m1, rmax1);
        const float al0 = fexp(m0 - mn0),   al1 = fexp(m1 - mn1);
        m0 = mn0; m1 = mn1;

        float rs0 = 0.f, rs1 = 0.f;
        uint32_t pah[4][4], pal[4][4];
#pragma unroll
        for (int n = 0; n < 8; n++) {
            float p0 = fexp(s[n][0] - mn0);
            float p1 = fexp(s[n][1] - mn0);
            float p2 = fexp(s[n][2] - mn1);
            float p3 = fexp(s[n][3] - mn1);
            rs0 += p0 + p1; rs1 += p2 + p3;
            const int kti = n >> 1, base = (n & 1) * 2;
            split_pack(p0, p1, pah[kti][base],     pal[kti][base]);
            split_pack(p2, p3, pah[kti][base + 1], pal[kti][base + 1]);
        }
        rs0 += __shfl_xor_sync(0xffffffffu, rs0, 1);
        rs0 += __shfl_xor_sync(0xffffffffu, rs0, 2);
        rs1 += __shfl_xor_sync(0xffffffffu, rs1, 1);
        rs1 += __shfl_xor_sync(0xffffffffu, rs1, 2);
        l0 = l0 * al0 + rs0;
        l1 = l1 * al1 + rs1;

#pragma unroll
        for (int n = 0; n < 16; n++) {
            O[n][0] *= al0; O[n][1] *= al0;
            O[n][2] *= al1; O[n][3] *= al1;
        }

        // ---- O += P V (x3) ----
#pragma unroll
        for (int np = 0; np < 8; np++) {
#pragma unroll
            for (int kk = 0; kk < 4; kk++) {
                uint32_t bh[4], bl[4];
                LDSM4(bh, saddr(&Vh[(np * 16 + rr) * SX + kk * 16 + cc8]));
                LDSM4(bl, saddr(&Vl[(np * 16 + rr) * SX + kk * 16 + cc8]));
                MMA(O[2 * np],     pah[kk], bh[0], bh[2]);
                MMA(O[2 * np],     pah[kk], bl[0], bl[2]);
                MMA(O[2 * np],     pal[kk], bh[0], bh[2]);
                MMA(O[2 * np + 1], pah[kk], bh[1], bh[3]);
                MMA(O[2 * np + 1], pah[kk], bl[1], bl[3]);
                MMA(O[2 * np + 1], pal[kk], bh[1], bh[3]);
            }
        }
    }

    // ---- write unnormalized partials + (m, l) ----
    float* Op = g_Op + (size_t)split * MT * HH;
    const int row0g = tb + qbase + warp * 16 + gid;
#pragma unroll
    for (int nt = 0; nt < 16; nt++) {
        const int h = nt * 8 + tig * 2;
        *(float2*)&Op[(size_t)row0g * HH + h]       = make_float2(O[nt][0], O[nt][1]);
        *(float2*)&Op[(size_t)(row0g + 8) * HH + h] = make_float2(O[nt][2], O[nt][3]);
    }
    if (tig == 0) {
        g_ML[split * MT + row0g]     = make_float2(m0, l0);
        g_ML[split * MT + row0g + 8] = make_float2(m1, l1);
    }
}

// ---------------- split-K combine ----------------
__global__ __launch_bounds__(256)
void combine(float* __restrict__ out) {
    const int token = blockIdx.x * 8 + (threadIdx.x >> 5);
    const int lane = threadIdx.x & 31;
    const float2 ml0 = g_ML[token];
    const float2 ml1 = g_ML[MT + token];
    const float m  = fmaxf(ml0.x, ml1.x);
    const float w0 = __expf(ml0.x - m), w1 = __expf(ml1.x - m);
    const float inv = 1.f / (ml0.y * w0 + ml1.y * w1);
    const float4 o0 = *(const float4*)&g_Op[(size_t)token * HH + lane * 4];
    const float4 o1 = *(const float4*)&g_Op[(size_t)(MT + token) * HH + lane * 4];
    float4 r;
    r.x = (o0.x * w0 + o1.x * w1) * inv;
    r.y = (o0.y * w0 + o1.y * w1) * inv;
    r.z = (o0.z * w0 + o1.z * w1) * inv;
    r.w = (o0.w * w0 + o1.w * w1) * inv;
    *(float4*)&out[(size_t)token * HH + lane * 4] = r;
}

// ---------------- launch ----------------
extern "C" void kernel_launch(void* const* d_in, const int* in_sizes, int n_in,
                              void* d_out, int out_size) {
    const float* x  = (const float*)d_in[0];
    const float* Wq = (const float*)d_in[1];
    const float* Wk = (const float*)d_in[2];
    const float* Wv = (const float*)d_in[3];
    float* out = (float*)d_out;

    conv_w<<<(3 * CC * HH + 255) / 256, 256>>>(Wq, Wk, Wv);

    const int PJ_SMEM = 4 * 128 * SX * (int)sizeof(__nv_bfloat16);   // 73728
    cudaFuncSetAttribute(proj_mma, cudaFuncAttributeMaxDynamicSharedMemorySize, PJ_SMEM);
    dim3 pg(MT / 128, 3);
    proj_mma<<<pg, 256, PJ_SMEM>>>(x, 0.08838834764831845f);

    const int AT_SMEM = (2 * 128 * SQ + 2 * 64 * SQ + 2 * 128 * SX) * (int)sizeof(__nv_bfloat16); // 141312
    cudaFuncSetAttribute(attn_mma, cudaFuncAttributeMaxDynamicSharedMemorySize, AT_SMEM);
    attn_mma<<<256, 256, AT_SMEM>>>();

    combine<<<MT / 8, 256>>>(out);
}

// round 5
// speedup vs baseline: 4.6209x; 1.1014x over previous
#include <cuda_runtime.h>
#include <cuda_bf16.h>
#include <stdint.h>

#define BB 4
#define TT 4096
#define CC 1024
#define HH 128
#define MT (BB * TT)

// ---------------- global scratch (allocation-free) ----------------
__device__ __nv_bfloat16 g_Wth[3 * HH * CC];   // transposed weights [mode][h][c], hi
__device__ __nv_bfloat16 g_Wtl[3 * HH * CC];   // lo
__device__ __nv_bfloat16 g_Qh[MT * HH], g_Ql[MT * HH];
__device__ __nv_bfloat16 g_Kh[MT * HH], g_Kl[MT * HH];
__device__ __nv_bfloat16 g_Vth[HH * MT], g_Vtl[HH * MT];   // V transposed [h][token]
__device__ float  g_Op[2 * MT * HH];           // split-K partial O (unnormalized)
__device__ float2 g_ML[2 * MT];                // split-K partial (m, l)

// ---------------- helpers ----------------
__device__ __forceinline__ uint32_t bpack(__nv_bfloat16 a, __nv_bfloat16 b) {
    return (uint32_t)__bfloat16_as_ushort(a) | ((uint32_t)__bfloat16_as_ushort(b) << 16);
}
__device__ __forceinline__ void split1(float v, __nv_bfloat16& h, __nv_bfloat16& l) {
    h = __float2bfloat16(v);
    l = __float2bfloat16(v - __bfloat162float(h));
}
__device__ __forceinline__ void split_pack(float a, float b, uint32_t& hi, uint32_t& lo) {
    __nv_bfloat16 ah, al_, bh, bl_;
    split1(a, ah, al_); split1(b, bh, bl_);
    hi = bpack(ah, bh); lo = bpack(al_, bl_);
}
// fast 2-float split via cvt.rn.bf16x2 + bit tricks (hi = {b16(b),b16(a)})
__device__ __forceinline__ void fsplit2(float a, float b, uint32_t& hi, uint32_t& lo) {
    uint32_t h;
    asm("cvt.rn.bf16x2.f32 %0, %1, %2;" : "=r"(h) : "f"(b), "f"(a));
    float ra = __uint_as_float(h << 16);
    float rb = __uint_as_float(h & 0xFFFF0000u);
    uint32_t l;
    asm("cvt.rn.bf16x2.f32 %0, %1, %2;" : "=r"(l) : "f"(b - rb), "f"(a - ra));
    hi = h; lo = l;
}
__device__ __forceinline__ uint32_t saddr(const void* p) {
    return (uint32_t)__cvta_generic_to_shared(p);
}
// exp via MUFU (off the FMA pipe). x <= 0 always here.
__device__ __forceinline__ float mexp(float x) {
    float r;
    asm("ex2.approx.ftz.f32 %0, %1;" : "=f"(r) : "f"(x * 1.4426950408889634f));
    return r;
}

#define MMA(d, a, b0_, b1_) asm volatile( \
    "mma.sync.aligned.m16n8k16.row.col.f32.bf16.bf16.f32 " \
    "{%0,%1,%2,%3}, {%4,%5,%6,%7}, {%8,%9}, {%0,%1,%2,%3};\n" \
    : "+f"(d[0]), "+f"(d[1]), "+f"(d[2]), "+f"(d[3]) \
    : "r"(a[0]), "r"(a[1]), "r"(a[2]), "r"(a[3]), "r"(b0_), "r"(b1_))

#define LDSM4(r, a) asm volatile( \
    "ldmatrix.sync.aligned.m8n8.x4.shared.b16 {%0,%1,%2,%3}, [%4];" \
    : "=r"((r)[0]), "=r"((r)[1]), "=r"((r)[2]), "=r"((r)[3]) : "r"(a))

#define CPA16(dst, src) asm volatile( \
    "cp.async.cg.shared.global [%0], [%1], 16;" :: "r"(dst), "l"(src) : "memory")
#define CPA_COMMIT() asm volatile("cp.async.commit_group;" ::: "memory")
#define CPA_WAIT1()  asm volatile("cp.async.wait_group 1;" ::: "memory")

// ---------------- weight conversion ----------------
__global__ void conv_w(const float* __restrict__ Wq, const float* __restrict__ Wk,
                       const float* __restrict__ Wv) {
    int i = blockIdx.x * blockDim.x + threadIdx.x;
    if (i >= 3 * CC * HH) return;
    int w = i / (CC * HH);
    int r = i % (CC * HH);
    int c = r / HH, h = r % HH;
    const float* W = (w == 0) ? Wq : (w == 1) ? Wk : Wv;
    __nv_bfloat16 bh, bl;
    split1(W[c * HH + h], bh, bl);
    g_Wth[w * HH * CC + h * CC + c] = bh;
    g_Wtl[w * HH * CC + h * CC + c] = bl;
}

// ---------------- fused projection GEMM (round-3 proven version) ----------
#define SX 72     // stride for 64-wide bf16 tiles
#define SQ 136    // stride for 128-wide bf16 tiles

#define PJ_PREFETCH(C0) do { \
    _Pragma("unroll") \
    for (int i_ = 0; i_ < 8; i_++) { \
        int idx_ = tid + i_ * 256; int r_ = idx_ >> 4, c4_ = (idx_ & 15) * 4; \
        xf[i_] = *(const float4*)&X[(size_t)(row0 + r_) * CC + (C0) + c4_]; \
    } \
    _Pragma("unroll") \
    for (int i_ = 0; i_ < 4; i_++) { \
        int idx_ = tid + i_ * 256; int r_ = idx_ >> 3, c8_ = (idx_ & 7) * 8; \
        wrh[i_] = *(const uint4*)&wbh[(size_t)r_ * CC + (C0) + c8_]; \
        wrl[i_] = *(const uint4*)&wbl[(size_t)r_ * CC + (C0) + c8_]; \
    } \
} while (0)

__global__ __launch_bounds__(256, 1)
void proj_mma(const float* __restrict__ X, float qscale) {
    extern __shared__ __nv_bfloat16 sm[];
    __nv_bfloat16* Xh = sm;                 // [128][SX]
    __nv_bfloat16* Xl = Xh + 128 * SX;
    __nv_bfloat16* Wh = Xl + 128 * SX;      // [128 h][SX]
    __nv_bfloat16* Wl = Wh + 128 * SX;

    const int tid = threadIdx.x, warp = tid >> 5, lane = tid & 31;
    const int gid = lane >> 2, tig = lane & 3;
    const int mode = blockIdx.y;
    const int row0 = blockIdx.x * 128;
    const __nv_bfloat16* wbh = g_Wth + (size_t)mode * HH * CC;
    const __nv_bfloat16* wbl = g_Wtl + (size_t)mode * HH * CC;

    float acc[16][4];
#pragma unroll
    for (int n = 0; n < 16; n++)
#pragma unroll
        for (int j = 0; j < 4; j++) acc[n][j] = 0.f;

    float4 xf[8]; uint4 wrh[4], wrl[4];
    PJ_PREFETCH(0);

    const int rr  = (lane & 7) + ((lane >> 3) & 1) * 8;
    const int cc8 = (lane >> 4) * 8;

    for (int c0 = 0; c0 < CC; c0 += 64) {
        __syncthreads();
#pragma unroll
        for (int i = 0; i < 8; i++) {
            int idx = tid + i * 256; int r = idx >> 4, c4 = (idx & 15) * 4;
            float4 v = xf[i];
            uint32_t h0, l0, h1, l1;
            fsplit2(v.x, v.y, h0, l0);
            fsplit2(v.z, v.w, h1, l1);
            *(uint32_t*)&Xh[r * SX + c4]     = h0;
            *(uint32_t*)&Xh[r * SX + c4 + 2] = h1;
            *(uint32_t*)&Xl[r * SX + c4]     = l0;
            *(uint32_t*)&Xl[r * SX + c4 + 2] = l1;
        }
#pragma unroll
        for (int i = 0; i < 4; i++) {
            int idx = tid + i * 256; int r = idx >> 3, c8 = (idx & 7) * 8;
            *(uint4*)&Wh[r * SX + c8] = wrh[i];
            *(uint4*)&Wl[r * SX + c8] = wrl[i];
        }
        __syncthreads();
        if (c0 + 64 < CC) { PJ_PREFETCH(c0 + 64); }

#pragma unroll
        for (int kt = 0; kt < 4; kt++) {
            const int kc = kt * 16;
            uint32_t ah[4], al[4];
            LDSM4(ah, saddr(&Xh[(warp * 16 + rr) * SX + kc + cc8]));
            LDSM4(al, saddr(&Xl[(warp * 16 + rr) * SX + kc + cc8]));
#pragma unroll
            for (int p = 0; p < 8; p++) {
                uint32_t bh[4], bl[4];
                LDSM4(bh, saddr(&Wh[(p * 16 + rr) * SX + kc + cc8]));
                LDSM4(bl, saddr(&Wl[(p * 16 + rr) * SX + kc + cc8]));
                MMA(acc[2 * p],     ah, bh[0], bh[2]);
                MMA(acc[2 * p],     ah, bl[0], bl[2]);
                MMA(acc[2 * p],     al, bh[0], bh[2]);
                MMA(acc[2 * p + 1], ah, bh[1], bh[3]);
                MMA(acc[2 * p + 1], ah, bl[1], bl[3]);
                MMA(acc[2 * p + 1], al, bh[1], bh[3]);
            }
        }
    }

    const float scale = (mode == 0) ? qscale : 1.0f;
    const int r0 = row0 + warp * 16 + gid;
    if (mode < 2) {
        __nv_bfloat16* oh = (mode == 0) ? g_Qh : g_Kh;
        __nv_bfloat16* ol = (mode == 0) ? g_Ql : g_Kl;
#pragma unroll
        for (int n = 0; n < 16; n++) {
            const int h = n * 8 + tig * 2;
            uint32_t hi, lo;
            split_pack(acc[n][0] * scale, acc[n][1] * scale, hi, lo);
            *(uint32_t*)&oh[(size_t)r0 * HH + h] = hi;
            *(uint32_t*)&ol[(size_t)r0 * HH + h] = lo;
            split_pack(acc[n][2] * scale, acc[n][3] * scale, hi, lo);
            *(uint32_t*)&oh[(size_t)(r0 + 8) * HH + h] = hi;
            *(uint32_t*)&ol[(size_t)(r0 + 8) * HH + h] = lo;
        }
    } else {
#pragma unroll
        for (int n = 0; n < 16; n++) {
            const int h = n * 8 + tig * 2;
            __nv_bfloat16 bh, bl;
            split1(acc[n][0], bh, bl); g_Vth[(size_t)h * MT + r0] = bh;           g_Vtl[(size_t)h * MT + r0] = bl;
            split1(acc[n][1], bh, bl); g_Vth[(size_t)(h + 1) * MT + r0] = bh;     g_Vtl[(size_t)(h + 1) * MT + r0] = bl;
            split1(acc[n][2], bh, bl); g_Vth[(size_t)h * MT + r0 + 8] = bh;       g_Vtl[(size_t)h * MT + r0 + 8] = bl;
            split1(acc[n][3], bh, bl); g_Vth[(size_t)(h + 1) * MT + r0 + 8] = bh; g_Vtl[(size_t)(h + 1) * MT + r0 + 8] = bl;
        }
    }
}

// ---------------- flash attention: BM=128, BN=64, split-K=2 -----------------
// Q fragments in registers. K/V double-buffered SMEM via cp.async.
// Stage (bytes): Kh@0 (17408), Kl@17408, Vh@34816 (18432), Vl@53248; size 71680.
// Q staged once at byte offset 71680 (Qh) / 106496 (Ql), then overwritten.
#define AT_STAGE 71680
#define AT_SMEM  (2 * AT_STAGE)   // 143360

#define AT_LOAD(KT, SB) do { \
    const int k0_ = (KT) * 64; \
    _Pragma("unroll") \
    for (int i_ = 0; i_ < 4; i_++) { \
        int idx_ = tid + i_ * 256; \
        int r_ = idx_ >> 4, c_ = (idx_ & 15) * 8; \
        CPA16((SB) + (uint32_t)(r_ * SQ + c_) * 2, \
              &g_Kh[(size_t)(tb + k0_ + r_) * HH + c_]); \
        CPA16((SB) + 17408u + (uint32_t)(r_ * SQ + c_) * 2, \
              &g_Kl[(size_t)(tb + k0_ + r_) * HH + c_]); \
        int vr_ = idx_ >> 3, vc_ = (idx_ & 7) * 8; \
        CPA16((SB) + 34816u + (uint32_t)(vr_ * SX + vc_) * 2, \
              &g_Vth[(size_t)vr_ * MT + tb + k0_ + vc_]); \
        CPA16((SB) + 53248u + (uint32_t)(vr_ * SX + vc_) * 2, \
              &g_Vtl[(size_t)vr_ * MT + tb + k0_ + vc_]); \
    } \
} while (0)

__global__ __launch_bounds__(256, 1)
void attn_mma() {
    extern __shared__ __align__(16) char dsm[];
    const uint32_t smem_u = saddr(dsm);

    const int tid = threadIdx.x, warp = tid >> 5, lane = tid & 31;
    const int gid = lane >> 2, tig = lane & 3;
    const int bx = blockIdx.x;
    const int qi    = 31 - (bx >> 3);        // heavy q-tiles first (LPT)
    const int b     = (bx >> 1) & 3;
    const int split = bx & 1;
    const int qbase = qi * 128, tb = b * TT;
    const int kt0 = split ? (qi + 1) : 0;
    const int kt1 = split ? (2 * qi + 2) : (qi + 1);

    const int rr  = (lane & 7) + ((lane >> 3) & 1) * 8;
    const int cc8 = (lane >> 4) * 8;

    // ---- stage Q into upper smem, then LDSM all fragments to registers ----
#pragma unroll
    for (int i = 0; i < 8; i++) {
        int idx = tid + i * 256; int r = idx >> 4, c = (idx & 15) * 8;
        *(uint4*)(dsm + AT_STAGE + (size_t)(r * SQ + c) * 2) =
            *(const uint4*)&g_Qh[(size_t)(tb + qbase + r) * HH + c];
        *(uint4*)(dsm + AT_STAGE + 34816 + (size_t)(r * SQ + c) * 2) =
            *(const uint4*)&g_Ql[(size_t)(tb + qbase + r) * HH + c];
    }
    __syncthreads();
    uint32_t qh[8][4], ql[8][4];
#pragma unroll
    for (int kk = 0; kk < 8; kk++) {
        const uint32_t off = (uint32_t)((warp * 16 + rr) * SQ + kk * 16 + cc8) * 2;
        LDSM4(qh[kk], smem_u + AT_STAGE + off);
        LDSM4(ql[kk], smem_u + AT_STAGE + 34816u + off);
    }
    __syncthreads();   // all warps done reading Q staging before cp.async overwrites

    // ---- prologue: fill both stages ----
    AT_LOAD(kt0, smem_u);
    CPA_COMMIT();
    if (kt0 + 1 < kt1) { AT_LOAD(kt0 + 1, smem_u + AT_STAGE); }
    CPA_COMMIT();

    float O[16][4];
#pragma unroll
    for (int n = 0; n < 16; n++)
#pragma unroll
        for (int j = 0; j < 4; j++) O[n][j] = 0.f;
    float m0 = -1e30f, m1 = -1e30f, l0 = 0.f, l1 = 0.f;

    for (int kt = kt0; kt < kt1; kt++) {
        CPA_WAIT1();
        __syncthreads();
        const uint32_t sb = smem_u + (uint32_t)((kt - kt0) & 1) * AT_STAGE;
        const int k0 = kt * 64;

        // ---- S = Q K^T (x3) ----
        float s[8][4];
#pragma unroll
        for (int n = 0; n < 8; n++)
#pragma unroll
            for (int j = 0; j < 4; j++) s[n][j] = 0.f;

#pragma unroll
        for (int kk = 0; kk < 8; kk++) {
            const uint32_t kc2 = (uint32_t)(kk * 16 + cc8) * 2;
#pragma unroll
            for (int p = 0; p < 4; p++) {
                uint32_t bh[4], bl[4];
                const uint32_t ro = (uint32_t)((p * 16 + rr) * SQ) * 2;
                LDSM4(bh, sb + ro + kc2);
                LDSM4(bl, sb + 17408u + ro + kc2);
                MMA(s[2 * p],     qh[kk], bh[0], bh[2]);
                MMA(s[2 * p],     qh[kk], bl[0], bl[2]);
                MMA(s[2 * p],     ql[kk], bh[0], bh[2]);
                MMA(s[2 * p + 1], qh[kk], bh[1], bh[3]);
                MMA(s[2 * p + 1], qh[kk], bl[1], bl[3]);
                MMA(s[2 * p + 1], ql[kk], bh[1], bh[3]);
            }
        }

        // ---- causal mask (tiles overlapping the diagonal) ----
        if (kt >= 2 * qi) {
            const int row0g = qbase + warp * 16 + gid;
#pragma unroll
            for (int n = 0; n < 8; n++) {
                const int keyg = k0 + n * 8 + tig * 2;
                if (keyg     > row0g)     s[n][0] = -3e30f;
                if (keyg + 1 > row0g)     s[n][1] = -3e30f;
                if (keyg     > row0g + 8) s[n][2] = -3e30f;
                if (keyg + 1 > row0g + 8) s[n][3] = -3e30f;
            }
        }

        // ---- online softmax ----
        float rmax0 = -3e30f, rmax1 = -3e30f;
#pragma unroll
        for (int n = 0; n < 8; n++) {
            rmax0 = fmaxf(rmax0, fmaxf(s[n][0], s[n][1]));
            rmax1 = fmaxf(rmax1, fmaxf(s[n][2], s[n][3]));
        }
        rmax0 = fmaxf(rmax0, __shfl_xor_sync(0xffffffffu, rmax0, 1));
        rmax0 = fmaxf(rmax0, __shfl_xor_sync(0xffffffffu, rmax0, 2));
        rmax1 = fmaxf(rmax1, __shfl_xor_sync(0xffffffffu, rmax1, 1));
        rmax1 = fmaxf(rmax1, __shfl_xor_sync(0xffffffffu, rmax1, 2));

        const float mn0 = fmaxf(m0, rmax0), mn1 = fmaxf(m1, rmax1);
        const float al0 = mexp(m0 - mn0),   al1 = mexp(m1 - mn1);
        m0 = mn0; m1 = mn1;

        float rs0 = 0.f, rs1 = 0.f;
        uint32_t pah[4][4], pal[4][4];
#pragma unroll
        for (int n = 0; n < 8; n++) {
            float p0 = mexp(s[n][0] - mn0);
            float p1 = mexp(s[n][1] - mn0);
            float p2 = mexp(s[n][2] - mn1);
            float p3 = mexp(s[n][3] - mn1);
            rs0 += p0 + p1; rs1 += p2 + p3;
            const int kti = n >> 1, base = (n & 1) * 2;
            fsplit2(p0, p1, pah[kti][base],     pal[kti][base]);
            fsplit2(p2, p3, pah[kti][base + 1], pal[kti][base + 1]);
        }
        rs0 += __shfl_xor_sync(0xffffffffu, rs0, 1);
        rs0 += __shfl_xor_sync(0xffffffffu, rs0, 2);
        rs1 += __shfl_xor_sync(0xffffffffu, rs1, 1);
        rs1 += __shfl_xor_sync(0xffffffffu, rs1, 2);
        l0 = l0 * al0 + rs0;
        l1 = l1 * al1 + rs1;

#pragma unroll
        for (int n = 0; n < 16; n++) {
            O[n][0] *= al0; O[n][1] *= al0;
            O[n][2] *= al1; O[n][3] *= al1;
        }

        // ---- O += P V (x3) ----
#pragma unroll
        for (int np = 0; np < 8; np++) {
#pragma unroll
            for (int kk = 0; kk < 4; kk++) {
                uint32_t bh[4], bl[4];
                const uint32_t vo = (uint32_t)((np * 16 + rr) * SX + kk * 16 + cc8) * 2;
                LDSM4(bh, sb + 34816u + vo);
                LDSM4(bl, sb + 53248u + vo);
                MMA(O[2 * np],     pah[kk], bh[0], bh[2]);
                MMA(O[2 * np],     pah[kk], bl[0], bl[2]);
                MMA(O[2 * np],     pal[kk], bh[0], bh[2]);
                MMA(O[2 * np + 1], pah[kk], bh[1], bh[3]);
                MMA(O[2 * np + 1], pah[kk], bl[1], bl[3]);
                MMA(O[2 * np + 1], pal[kk], bh[1], bh[3]);
            }
        }

        __syncthreads();   // all warps done reading this stage
        if (kt + 2 < kt1) { AT_LOAD(kt + 2, sb); }
        CPA_COMMIT();
    }

    // ---- write unnormalized partials + (m, l) ----
    float* Op = g_Op + (size_t)split * MT * HH;
    const int row0g = tb + qbase + warp * 16 + gid;
#pragma unroll
    for (int nt = 0; nt < 16; nt++) {
        const int h = nt * 8 + tig * 2;
        *(float2*)&Op[(size_t)row0g * HH + h]       = make_float2(O[nt][0], O[nt][1]);
        *(float2*)&Op[(size_t)(row0g + 8) * HH + h] = make_float2(O[nt][2], O[nt][3]);
    }
    if (tig == 0) {
        g_ML[split * MT + row0g]     = make_float2(m0, l0);
        g_ML[split * MT + row0g + 8] = make_float2(m1, l1);
    }
}

// ---------------- split-K combine ----------------
__global__ __launch_bounds__(256)
void combine(float* __restrict__ out) {
    const int token = blockIdx.x * 8 + (threadIdx.x >> 5);
    const int lane = threadIdx.x & 31;
    const float2 ml0 = g_ML[token];
    const float2 ml1 = g_ML[MT + token];
    const float m  = fmaxf(ml0.x, ml1.x);
    const float w0 = __expf(ml0.x - m), w1 = __expf(ml1.x - m);
    const float inv = 1.f / (ml0.y * w0 + ml1.y * w1);
    const float4 o0 = *(const float4*)&g_Op[(size_t)token * HH + lane * 4];
    const float4 o1 = *(const float4*)&g_Op[(size_t)(MT + token) * HH + lane * 4];
    float4 r;
    r.x = (o0.x * w0 + o1.x * w1) * inv;
    r.y = (o0.y * w0 + o1.y * w1) * inv;
    r.z = (o0.z * w0 + o1.z * w1) * inv;
    r.w = (o0.w * w0 + o1.w * w1) * inv;
    *(float4*)&out[(size_t)token * HH + lane * 4] = r;
}

// ---------------- launch ----------------
extern "C" void kernel_launch(void* const* d_in, const int* in_sizes, int n_in,
                              void* d_out, int out_size) {
    const float* x  = (const float*)d_in[0];
    const float* Wq = (const float*)d_in[1];
    const float* Wk = (const float*)d_in[2];
    const float* Wv = (const float*)d_in[3];
    float* out = (float*)d_out;

    conv_w<<<(3 * CC * HH + 255) / 256, 256>>>(Wq, Wk, Wv);

    const int PJ_SMEM = 4 * 128 * SX * (int)sizeof(__nv_bfloat16);   // 73728
    cudaFuncSetAttribute(proj_mma, cudaFuncAttributeMaxDynamicSharedMemorySize, PJ_SMEM);
    dim3 pg(MT / 128, 3);
    proj_mma<<<pg, 256, PJ_SMEM>>>(x, 0.08838834764831845f);

    cudaFuncSetAttribute(attn_mma, cudaFuncAttributeMaxDynamicSharedMemorySize, AT_SMEM);
    attn_mma<<<256, 256, AT_SMEM>>>();

    combine<<<MT / 8, 256>>>(out);
}

// round 7
// speedup vs baseline: 9.3553x; 2.0246x over previous
#include <cuda_runtime.h>
#include <cuda_fp16.h>
#include <stdint.h>

#define BB 4
#define TT 4096
#define CC 1024
#define HH 128
#define MT (BB * TT)

// ---------------- global scratch (allocation-free) ----------------
__device__ __half g_Wt[3 * HH * CC];     // transposed weights [mode][h][c]
__device__ __half g_Q[MT * HH];
__device__ __half g_K[MT * HH];
__device__ __half g_Vt[HH * MT];         // V transposed [h][token]
__device__ float  g_Op[2 * MT * HH];     // split-K partial O (unnormalized)
__device__ float2 g_ML[2 * MT];          // split-K partial (m, l)

// ---------------- helpers ----------------
__device__ __forceinline__ uint32_t hpack(float a, float b) {
    __half2 h = __floats2half2_rn(a, b);
    return *(uint32_t*)&h;
}
__device__ __forceinline__ uint32_t saddr(const void* p) {
    return (uint32_t)__cvta_generic_to_shared(p);
}
// fast exp on the FMA pipe (x <= ~0). rel err ~2e-7.
__device__ __forceinline__ float fexp(float x) {
    float y = fmaxf(x * 1.4426950408889634f, -126.0f);
    float t = y + 12582912.0f;
    float fi = t - 12582912.0f;
    float z  = (y - fi) * 0.6931471805599453f;
    float p = 1.3888888889e-3f;
    p = fmaf(p, z, 8.3333333333e-3f);
    p = fmaf(p, z, 4.1666666667e-2f);
    p = fmaf(p, z, 1.6666666667e-1f);
    p = fmaf(p, z, 0.5f);
    p = fmaf(p, z, 1.0f);
    p = fmaf(p, z, 1.0f);
    int e = __float_as_int(t) - 0x4B400000;
    float sc = __int_as_float((e + 127) << 23);
    return p * sc;
}

#define MMAH(d, a, b0_, b1_) asm volatile( \
    "mma.sync.aligned.m16n8k16.row.col.f32.f16.f16.f32 " \
    "{%0,%1,%2,%3}, {%4,%5,%6,%7}, {%8,%9}, {%0,%1,%2,%3};\n" \
    : "+f"(d[0]), "+f"(d[1]), "+f"(d[2]), "+f"(d[3]) \
    : "r"(a[0]), "r"(a[1]), "r"(a[2]), "r"(a[3]), "r"(b0_), "r"(b1_))

#define LDSM4(r, a) asm volatile( \
    "ldmatrix.sync.aligned.m8n8.x4.shared.b16 {%0,%1,%2,%3}, [%4];" \
    : "=r"((r)[0]), "=r"((r)[1]), "=r"((r)[2]), "=r"((r)[3]) : "r"(a))

#define CPA16(dst, src) asm volatile( \
    "cp.async.cg.shared.global [%0], [%1], 16;" :: "r"(dst), "l"(src) : "memory")
#define CPA_COMMIT() asm volatile("cp.async.commit_group;" ::: "memory")
#define CPA_WAIT1()  asm volatile("cp.async.wait_group 1;" ::: "memory")

// ---------------- weight conversion ----------------
__global__ void conv_w(const float* __restrict__ Wq, const float* __restrict__ Wk,
                       const float* __restrict__ Wv) {
    int i = blockIdx.x * blockDim.x + threadIdx.x;
    if (i >= 3 * CC * HH) return;
    int w = i / (CC * HH);
    int r = i % (CC * HH);
    int c = r / HH, h = r % HH;
    const float* W = (w == 0) ? Wq : (w == 1) ? Wk : Wv;
    g_Wt[w * HH * CC + h * CC + c] = __float2half(W[c * HH + h]);
}

// ---------------- fused projection GEMM (fp16 x1) -------------------------
#define SX 72     // stride (halves) for 64-wide tiles
#define SQ 136    // stride (halves) for 128-wide tiles

#define PJ_PREFETCH(C0) do { \
    _Pragma("unroll") \
    for (int i_ = 0; i_ < 8; i_++) { \
        int idx_ = tid + i_ * 256; int r_ = idx_ >> 4, c4_ = (idx_ & 15) * 4; \
        xf[i_] = *(const float4*)&X[(size_t)(row0 + r_) * CC + (C0) + c4_]; \
    } \
    _Pragma("unroll") \
    for (int i_ = 0; i_ < 4; i_++) { \
        int idx_ = tid + i_ * 256; int r_ = idx_ >> 3, c8_ = (idx_ & 7) * 8; \
        wr[i_] = *(const uint4*)&wb[(size_t)r_ * CC + (C0) + c8_]; \
    } \
} while (0)

__global__ __launch_bounds__(256, 1)
void proj_mma(const float* __restrict__ X, float qscale) {
    extern __shared__ __half sm[];
    __half* Xs = sm;                 // [128][SX]
    __half* Ws = Xs + 128 * SX;      // [128 h][SX]

    const int tid = threadIdx.x, warp = tid >> 5, lane = tid & 31;
    const int gid = lane >> 2, tig = lane & 3;
    const int mode = blockIdx.y;
    const int row0 = blockIdx.x * 128;
    const __half* wb = g_Wt + (size_t)mode * HH * CC;

    float acc[16][4];
#pragma unroll
    for (int n = 0; n < 16; n++)
#pragma unroll
        for (int j = 0; j < 4; j++) acc[n][j] = 0.f;

    float4 xf[8]; uint4 wr[4];
    PJ_PREFETCH(0);

    const int rr  = (lane & 7) + ((lane >> 3) & 1) * 8;
    const int cc8 = (lane >> 4) * 8;

    for (int c0 = 0; c0 < CC; c0 += 64) {
        __syncthreads();
#pragma unroll
        for (int i = 0; i < 8; i++) {
            int idx = tid + i * 256; int r = idx >> 4, c4 = (idx & 15) * 4;
            float4 v = xf[i];
            *(uint32_t*)&Xs[r * SX + c4]     = hpack(v.x, v.y);
            *(uint32_t*)&Xs[r * SX + c4 + 2] = hpack(v.z, v.w);
        }
#pragma unroll
        for (int i = 0; i < 4; i++) {
            int idx = tid + i * 256; int r = idx >> 3, c8 = (idx & 7) * 8;
            *(uint4*)&Ws[r * SX + c8] = wr[i];
        }
        __syncthreads();
        if (c0 + 64 < CC) { PJ_PREFETCH(c0 + 64); }

#pragma unroll
        for (int kt = 0; kt < 4; kt++) {
            const int kc = kt * 16;
            uint32_t a[4];
            LDSM4(a, saddr(&Xs[(warp * 16 + rr) * SX + kc + cc8]));
#pragma unroll
            for (int p = 0; p < 8; p++) {
                uint32_t b[4];
                LDSM4(b, saddr(&Ws[(p * 16 + rr) * SX + kc + cc8]));
                MMAH(acc[2 * p],     a, b[0], b[2]);
                MMAH(acc[2 * p + 1], a, b[1], b[3]);
            }
        }
    }

    const float scale = (mode == 0) ? qscale : 1.0f;
    const int r0 = row0 + warp * 16 + gid;
    if (mode < 2) {
        __half* o = (mode == 0) ? g_Q : g_K;
#pragma unroll
        for (int n = 0; n < 16; n++) {
            const int h = n * 8 + tig * 2;
            *(uint32_t*)&o[(size_t)r0 * HH + h] =
                hpack(acc[n][0] * scale, acc[n][1] * scale);
            *(uint32_t*)&o[(size_t)(r0 + 8) * HH + h] =
                hpack(acc[n][2] * scale, acc[n][3] * scale);
        }
    } else {   // V transposed [h][token]
#pragma unroll
        for (int n = 0; n < 16; n++) {
            const int h = n * 8 + tig * 2;
            g_Vt[(size_t)h * MT + r0]           = __float2half(acc[n][0]);
            g_Vt[(size_t)(h + 1) * MT + r0]     = __float2half(acc[n][1]);
            g_Vt[(size_t)h * MT + r0 + 8]       = __float2half(acc[n][2]);
            g_Vt[(size_t)(h + 1) * MT + r0 + 8] = __float2half(acc[n][3]);
        }
    }
}

// ---------------- flash attention: BM=128, BN=64, split-K=2, fp16 x1 -------
// Stage (bytes): K@0 (17408 = 64*SQ*2), V@17408 (18432 = 128*SX*2); stage 35840.
// Q staged once into stage0 region before the pipeline starts.
#define AT_STAGE 35840
#define AT_SMEM  (2 * AT_STAGE)   // 71680

#define AT_LOAD(KT, SB) do { \
    const int k0_ = (KT) * 64; \
    _Pragma("unroll") \
    for (int i_ = 0; i_ < 4; i_++) { \
        int idx_ = tid + i_ * 256; \
        int r_ = idx_ >> 4, c_ = (idx_ & 15) * 8; \
        CPA16((SB) + (uint32_t)(r_ * SQ + c_) * 2, \
              &g_K[(size_t)(tb + k0_ + r_) * HH + c_]); \
        int vr_ = idx_ >> 3, vc_ = (idx_ & 7) * 8; \
        CPA16((SB) + 17408u + (uint32_t)(vr_ * SX + vc_) * 2, \
              &g_Vt[(size_t)vr_ * MT + tb + k0_ + vc_]); \
    } \
} while (0)

__global__ __launch_bounds__(256, 1)
void attn_mma() {
    extern __shared__ __align__(16) char dsm[];
    const uint32_t smem_u = saddr(dsm);

    const int tid = threadIdx.x, warp = tid >> 5, lane = tid & 31;
    const int gid = lane >> 2, tig = lane & 3;
    const int bx = blockIdx.x;
    const int qi    = 31 - (bx >> 3);        // heavy q-tiles first (LPT)
    const int b     = (bx >> 1) & 3;
    const int split = bx & 1;
    const int qbase = qi * 128, tb = b * TT;
    const int kt0 = split ? (qi + 1) : 0;
    const int kt1 = split ? (2 * qi + 2) : (qi + 1);

    const int rr  = (lane & 7) + ((lane >> 3) & 1) * 8;
    const int cc8 = (lane >> 4) * 8;

    // ---- stage Q: 128 rows x 128 halves = 2048 uint4 -> i < 8 (bug fix) ----
#pragma unroll
    for (int i = 0; i < 8; i++) {
        int idx = tid + i * 256; int r = idx >> 4, c = (idx & 15) * 8;
        *(uint4*)(dsm + (size_t)(r * SQ + c) * 2) =
            *(const uint4*)&g_Q[(size_t)(tb + qbase + r) * HH + c];
    }
    __syncthreads();
    uint32_t qf[8][4];
#pragma unroll
    for (int kk = 0; kk < 8; kk++) {
        LDSM4(qf[kk], smem_u + (uint32_t)((warp * 16 + rr) * SQ + kk * 16 + cc8) * 2);
    }
    __syncthreads();   // Q fragments safe before cp.async overwrites stage0

    // ---- prologue: fill both stages ----
    AT_LOAD(kt0, smem_u);
    CPA_COMMIT();
    if (kt0 + 1 < kt1) { AT_LOAD(kt0 + 1, smem_u + AT_STAGE); }
    CPA_COMMIT();

    float O[16][4];
#pragma unroll
    for (int n = 0; n < 16; n++)
#pragma unroll
        for (int j = 0; j < 4; j++) O[n][j] = 0.f;
    float m0 = -1e30f, m1 = -1e30f, l0 = 0.f, l1 = 0.f;

    for (int kt = kt0; kt < kt1; kt++) {
        CPA_WAIT1();
        __syncthreads();
        const uint32_t sb = smem_u + (uint32_t)((kt - kt0) & 1) * AT_STAGE;
        const int k0 = kt * 64;

        // ---- S = Q K^T ----
        float s[8][4];
#pragma unroll
        for (int n = 0; n < 8; n++)
#pragma unroll
            for (int j = 0; j < 4; j++) s[n][j] = 0.f;

#pragma unroll
        for (int kk = 0; kk < 8; kk++) {
            const uint32_t kc2 = (uint32_t)(kk * 16 + cc8) * 2;
#pragma unroll
            for (int p = 0; p < 4; p++) {
                uint32_t kb[4];
                LDSM4(kb, sb + (uint32_t)((p * 16 + rr) * SQ) * 2 + kc2);
                MMAH(s[2 * p],     qf[kk], kb[0], kb[2]);
                MMAH(s[2 * p + 1], qf[kk], kb[1], kb[3]);
            }
        }

        // ---- causal mask ----
        if (kt >= 2 * qi) {
            const int row0g = qbase + warp * 16 + gid;
#pragma unroll
            for (int n = 0; n < 8; n++) {
                const int keyg = k0 + n * 8 + tig * 2;
                if (keyg     > row0g)     s[n][0] = -3e30f;
                if (keyg + 1 > row0g)     s[n][1] = -3e30f;
                if (keyg     > row0g + 8) s[n][2] = -3e30f;
                if (keyg + 1 > row0g + 8) s[n][3] = -3e30f;
            }
        }

        // ---- online softmax ----
        float rmax0 = -3e30f, rmax1 = -3e30f;
#pragma unroll
        for (int n = 0; n < 8; n++) {
            rmax0 = fmaxf(rmax0, fmaxf(s[n][0], s[n][1]));
            rmax1 = fmaxf(rmax1, fmaxf(s[n][2], s[n][3]));
        }
        rmax0 = fmaxf(rmax0, __shfl_xor_sync(0xffffffffu, rmax0, 1));
        rmax0 = fmaxf(rmax0, __shfl_xor_sync(0xffffffffu, rmax0, 2));
        rmax1 = fmaxf(rmax1, __shfl_xor_sync(0xffffffffu, rmax1, 1));
        rmax1 = fmaxf(rmax1, __shfl_xor_sync(0xffffffffu, rmax1, 2));

        const float mn0 = fmaxf(m0, rmax0), mn1 = fmaxf(m1, rmax1);
        const float al0 = fexp(m0 - mn0),   al1 = fexp(m1 - mn1);
        m0 = mn0; m1 = mn1;

        float rs0 = 0.f, rs1 = 0.f;
        uint32_t pf[4][4];
#pragma unroll
        for (int n = 0; n < 8; n++) {
            float p0 = fexp(s[n][0] - mn0);
            float p1 = fexp(s[n][1] - mn0);
            float p2 = fexp(s[n][2] - mn1);
            float p3 = fexp(s[n][3] - mn1);
            rs0 += p0 + p1; rs1 += p2 + p3;
            const int kti = n >> 1, base = (n & 1) * 2;
            pf[kti][base]     = hpack(p0, p1);
            pf[kti][base + 1] = hpack(p2, p3);
        }
        rs0 += __shfl_xor_sync(0xffffffffu, rs0, 1);
        rs0 += __shfl_xor_sync(0xffffffffu, rs0, 2);
        rs1 += __shfl_xor_sync(0xffffffffu, rs1, 1);
        rs1 += __shfl_xor_sync(0xffffffffu, rs1, 2);
        l0 = l0 * al0 + rs0;
        l1 = l1 * al1 + rs1;

#pragma unroll
        for (int n = 0; n < 16; n++) {
            O[n][0] *= al0; O[n][1] *= al0;
            O[n][2] *= al1; O[n][3] *= al1;
        }

        // ---- O += P V ----
#pragma unroll
        for (int np = 0; np < 8; np++) {
#pragma unroll
            for (int kk = 0; kk < 4; kk++) {
                uint32_t vb[4];
                LDSM4(vb, sb + 17408u +
                          (uint32_t)((np * 16 + rr) * SX + kk * 16 + cc8) * 2);
                MMAH(O[2 * np],     pf[kk], vb[0], vb[2]);
                MMAH(O[2 * np + 1], pf[kk], vb[1], vb[3]);
            }
        }

        __syncthreads();   // all warps done reading this stage
        if (kt + 2 < kt1) { AT_LOAD(kt + 2, sb); }
        CPA_COMMIT();
    }

    // ---- write unnormalized partials + (m, l) ----
    float* Op = g_Op + (size_t)split * MT * HH;
    const int row0g = tb + qbase + warp * 16 + gid;
#pragma unroll
    for (int nt = 0; nt < 16; nt++) {
        const int h = nt * 8 + tig * 2;
        *(float2*)&Op[(size_t)row0g * HH + h]       = make_float2(O[nt][0], O[nt][1]);
        *(float2*)&Op[(size_t)(row0g + 8) * HH + h] = make_float2(O[nt][2], O[nt][3]);
    }
    if (tig == 0) {
        g_ML[split * MT + row0g]     = make_float2(m0, l0);
        g_ML[split * MT + row0g + 8] = make_float2(m1, l1);
    }
}

// ---------------- split-K combine ----------------
__global__ __launch_bounds__(256)
void combine(float* __restrict__ out) {
    const int token = blockIdx.x * 8 + (threadIdx.x >> 5);
    const int lane = threadIdx.x & 31;
    const float2 ml0 = g_ML[token];
    const float2 ml1 = g_ML[MT + token];
    const float m  = fmaxf(ml0.x, ml1.x);
    const float w0 = __expf(ml0.x - m), w1 = __expf(ml1.x - m);
    const float inv = 1.f / (ml0.y * w0 + ml1.y * w1);
    const float4 o0 = *(const float4*)&g_Op[(size_t)token * HH + lane * 4];
    const float4 o1 = *(const float4*)&g_Op[(size_t)(MT + token) * HH + lane * 4];
    float4 r;
    r.x = (o0.x * w0 + o1.x * w1) * inv;
    r.y = (o0.y * w0 + o1.y * w1) * inv;
    r.z = (o0.z * w0 + o1.z * w1) * inv;
    r.w = (o0.w * w0 + o1.w * w1) * inv;
    *(float4*)&out[(size_t)token * HH + lane * 4] = r;
}

// ---------------- launch ----------------
extern "C" void kernel_launch(void* const* d_in, const int* in_sizes, int n_in,
                              void* d_out, int out_size) {
    const float* x  = (const float*)d_in[0];
    const float* Wq = (const float*)d_in[1];
    const float* Wk = (const float*)d_in[2];
    const float* Wv = (const float*)d_in[3];
    float* out = (float*)d_out;

    conv_w<<<(3 * CC * HH + 255) / 256, 256>>>(Wq, Wk, Wv);

    const int PJ_SMEM = 2 * 128 * SX * (int)sizeof(__half);   // 36864
    cudaFuncSetAttribute(proj_mma, cudaFuncAttributeMaxDynamicSharedMemorySize, PJ_SMEM);
    dim3 pg(MT / 128, 3);
    proj_mma<<<pg, 256, PJ_SMEM>>>(x, 0.08838834764831845f);

    cudaFuncSetAttribute(attn_mma, cudaFuncAttributeMaxDynamicSharedMemorySize, AT_SMEM);
    attn_mma<<<256, 256, AT_SMEM>>>();

    combine<<<MT / 8, 256>>>(out);
}

// round 8
// speedup vs baseline: 9.3822x; 1.0029x over previous
#include <cuda_runtime.h>
#include <cuda_fp16.h>
#include <stdint.h>

#define BB 4
#define TT 4096
#define CC 1024
#define HH 128
#define MT (BB * TT)

// ---------------- global scratch (allocation-free) ----------------
__device__ __half g_Wt[3 * HH * CC];     // transposed weights [mode][h][c]
__device__ __half g_Q[MT * HH];
__device__ __half g_K[MT * HH];
__device__ __half g_Vt[HH * MT];         // V transposed [h][token]
__device__ float  g_Op[2 * MT * HH];     // split-K partial O (unnormalized)
__device__ float2 g_ML[2 * MT];          // split-K partial (m, l)

// ---------------- helpers ----------------
__device__ __forceinline__ uint32_t hpack(float a, float b) {
    __half2 h = __floats2half2_rn(a, b);
    return *(uint32_t*)&h;
}
__device__ __forceinline__ uint32_t saddr(const void* p) {
    return (uint32_t)__cvta_generic_to_shared(p);
}
// fast exp on the FMA pipe (x <= ~0). rel err ~2e-7.
__device__ __forceinline__ float fexp(float x) {
    float y = fmaxf(x * 1.4426950408889634f, -126.0f);
    float t = y + 12582912.0f;
    float fi = t - 12582912.0f;
    float z  = (y - fi) * 0.6931471805599453f;
    float p = 1.3888888889e-3f;
    p = fmaf(p, z, 8.3333333333e-3f);
    p = fmaf(p, z, 4.1666666667e-2f);
    p = fmaf(p, z, 1.6666666667e-1f);
    p = fmaf(p, z, 0.5f);
    p = fmaf(p, z, 1.0f);
    p = fmaf(p, z, 1.0f);
    int e = __float_as_int(t) - 0x4B400000;
    float sc = __int_as_float((e + 127) << 23);
    return p * sc;
}

#define MMAH(d, a, b0_, b1_) asm volatile( \
    "mma.sync.aligned.m16n8k16.row.col.f32.f16.f16.f32 " \
    "{%0,%1,%2,%3}, {%4,%5,%6,%7}, {%8,%9}, {%0,%1,%2,%3};\n" \
    : "+f"(d[0]), "+f"(d[1]), "+f"(d[2]), "+f"(d[3]) \
    : "r"(a[0]), "r"(a[1]), "r"(a[2]), "r"(a[3]), "r"(b0_), "r"(b1_))

#define LDSM4(r, a) asm volatile( \
    "ldmatrix.sync.aligned.m8n8.x4.shared.b16 {%0,%1,%2,%3}, [%4];" \
    : "=r"((r)[0]), "=r"((r)[1]), "=r"((r)[2]), "=r"((r)[3]) : "r"(a))

#define CPA16(dst, src) asm volatile( \
    "cp.async.cg.shared.global [%0], [%1], 16;" :: "r"(dst), "l"(src) : "memory")
#define CPA_COMMIT() asm volatile("cp.async.commit_group;" ::: "memory")
#define CPA_WAIT1()  asm volatile("cp.async.wait_group 1;" ::: "memory")

// ---------------- weight conversion ----------------
__global__ void conv_w(const float* __restrict__ Wq, const float* __restrict__ Wk,
                       const float* __restrict__ Wv) {
    int i = blockIdx.x * blockDim.x + threadIdx.x;
    if (i >= 3 * CC * HH) return;
    int w = i / (CC * HH);
    int r = i % (CC * HH);
    int c = r / HH, h = r % HH;
    const float* W = (w == 0) ? Wq : (w == 1) ? Wk : Wv;
    g_Wt[w * HH * CC + h * CC + c] = __float2half(W[c * HH + h]);
}

// ---------------- fused projection GEMM (fp16 x1, unchanged from R7) -------
#define SX 72     // stride (halves) for 64-wide tiles
#define SQ 136    // stride (halves) for 128-wide tiles

#define PJ_PREFETCH(C0) do { \
    _Pragma("unroll") \
    for (int i_ = 0; i_ < 8; i_++) { \
        int idx_ = tid + i_ * 256; int r_ = idx_ >> 4, c4_ = (idx_ & 15) * 4; \
        xf[i_] = *(const float4*)&X[(size_t)(row0 + r_) * CC + (C0) + c4_]; \
    } \
    _Pragma("unroll") \
    for (int i_ = 0; i_ < 4; i_++) { \
        int idx_ = tid + i_ * 256; int r_ = idx_ >> 3, c8_ = (idx_ & 7) * 8; \
        wr[i_] = *(const uint4*)&wb[(size_t)r_ * CC + (C0) + c8_]; \
    } \
} while (0)

__global__ __launch_bounds__(256, 1)
void proj_mma(const float* __restrict__ X, float qscale) {
    extern __shared__ __half sm[];
    __half* Xs = sm;                 // [128][SX]
    __half* Ws = Xs + 128 * SX;      // [128 h][SX]

    const int tid = threadIdx.x, warp = tid >> 5, lane = tid & 31;
    const int gid = lane >> 2, tig = lane & 3;
    const int mode = blockIdx.y;
    const int row0 = blockIdx.x * 128;
    const __half* wb = g_Wt + (size_t)mode * HH * CC;

    float acc[16][4];
#pragma unroll
    for (int n = 0; n < 16; n++)
#pragma unroll
        for (int j = 0; j < 4; j++) acc[n][j] = 0.f;

    float4 xf[8]; uint4 wr[4];
    PJ_PREFETCH(0);

    const int rr  = (lane & 7) + ((lane >> 3) & 1) * 8;
    const int cc8 = (lane >> 4) * 8;

    for (int c0 = 0; c0 < CC; c0 += 64) {
        __syncthreads();
#pragma unroll
        for (int i = 0; i < 8; i++) {
            int idx = tid + i * 256; int r = idx >> 4, c4 = (idx & 15) * 4;
            float4 v = xf[i];
            *(uint32_t*)&Xs[r * SX + c4]     = hpack(v.x, v.y);
            *(uint32_t*)&Xs[r * SX + c4 + 2] = hpack(v.z, v.w);
        }
#pragma unroll
        for (int i = 0; i < 4; i++) {
            int idx = tid + i * 256; int r = idx >> 3, c8 = (idx & 7) * 8;
            *(uint4*)&Ws[r * SX + c8] = wr[i];
        }
        __syncthreads();
        if (c0 + 64 < CC) { PJ_PREFETCH(c0 + 64); }

#pragma unroll
        for (int kt = 0; kt < 4; kt++) {
            const int kc = kt * 16;
            uint32_t a[4];
            LDSM4(a, saddr(&Xs[(warp * 16 + rr) * SX + kc + cc8]));
#pragma unroll
            for (int p = 0; p < 8; p++) {
                uint32_t b[4];
                LDSM4(b, saddr(&Ws[(p * 16 + rr) * SX + kc + cc8]));
                MMAH(acc[2 * p],     a, b[0], b[2]);
                MMAH(acc[2 * p + 1], a, b[1], b[3]);
            }
        }
    }

    const float scale = (mode == 0) ? qscale : 1.0f;
    const int r0 = row0 + warp * 16 + gid;
    if (mode < 2) {
        __half* o = (mode == 0) ? g_Q : g_K;
#pragma unroll
        for (int n = 0; n < 16; n++) {
            const int h = n * 8 + tig * 2;
            *(uint32_t*)&o[(size_t)r0 * HH + h] =
                hpack(acc[n][0] * scale, acc[n][1] * scale);
            *(uint32_t*)&o[(size_t)(r0 + 8) * HH + h] =
                hpack(acc[n][2] * scale, acc[n][3] * scale);
        }
    } else {   // V transposed [h][token]
#pragma unroll
        for (int n = 0; n < 16; n++) {
            const int h = n * 8 + tig * 2;
            g_Vt[(size_t)h * MT + r0]           = __float2half(acc[n][0]);
            g_Vt[(size_t)(h + 1) * MT + r0]     = __float2half(acc[n][1]);
            g_Vt[(size_t)h * MT + r0 + 8]       = __float2half(acc[n][2]);
            g_Vt[(size_t)(h + 1) * MT + r0 + 8] = __float2half(acc[n][3]);
        }
    }
}

// ---------------- flash attention: BM=64, BN=64, split-K=2, 2 CTAs/SM ------
// 128 threads (4 warps, 16 q-rows each). Stage (bytes): K@0 (17408 = 64*SQ*2),
// V@17408 (18432 = 128*SX*2); stage 35840, double-buffered = 71680/CTA.
#define AT_STAGE 35840
#define AT_SMEM  (2 * AT_STAGE)   // 71680

#define AT_LOAD(KT, SB) do { \
    const int k0_ = (KT) * 64; \
    _Pragma("unroll") \
    for (int i_ = 0; i_ < 8; i_++) { \
        int idx_ = tid + i_ * 128; \
        int r_ = idx_ >> 4, c_ = (idx_ & 15) * 8; \
        CPA16((SB) + (uint32_t)(r_ * SQ + c_) * 2, \
              &g_K[(size_t)(tb + k0_ + r_) * HH + c_]); \
        int vr_ = idx_ >> 3, vc_ = (idx_ & 7) * 8; \
        CPA16((SB) + 17408u + (uint32_t)(vr_ * SX + vc_) * 2, \
              &g_Vt[(size_t)vr_ * MT + tb + k0_ + vc_]); \
    } \
} while (0)

__global__ __launch_bounds__(128, 2)
void attn_mma() {
    extern __shared__ __align__(16) char dsm[];
    const uint32_t smem_u = saddr(dsm);

    const int tid = threadIdx.x, warp = tid >> 5, lane = tid & 31;
    const int gid = lane >> 2, tig = lane & 3;
    const int bx = blockIdx.x;
    const int qi    = 63 - (bx >> 3);        // heavy q-tiles first (LPT)
    const int b     = (bx >> 1) & 3;
    const int split = bx & 1;
    const int qbase = qi * 64, tb = b * TT;
    const int nk  = qi + 1;                   // visible key tiles
    const int kt0 = split ? (nk >> 1) : 0;
    const int kt1 = split ? nk : (nk >> 1);

    const int rr  = (lane & 7) + ((lane >> 3) & 1) * 8;
    const int cc8 = (lane >> 4) * 8;

    // ---- stage Q (64 rows x 128 halves = 1024 uint4), grab fragments ----
#pragma unroll
    for (int i = 0; i < 8; i++) {
        int idx = tid + i * 128; int r = idx >> 4, c = (idx & 15) * 8;
        *(uint4*)(dsm + (size_t)(r * SQ + c) * 2) =
            *(const uint4*)&g_Q[(size_t)(tb + qbase + r) * HH + c];
    }
    __syncthreads();
    uint32_t qf[8][4];
#pragma unroll
    for (int kk = 0; kk < 8; kk++) {
        LDSM4(qf[kk], smem_u + (uint32_t)((warp * 16 + rr) * SQ + kk * 16 + cc8) * 2);
    }
    __syncthreads();   // Q fragments safe before cp.async overwrites stage0

    // ---- prologue: fill both stages ----
    if (kt0 < kt1)     { AT_LOAD(kt0, smem_u); }
    CPA_COMMIT();
    if (kt0 + 1 < kt1) { AT_LOAD(kt0 + 1, smem_u + AT_STAGE); }
    CPA_COMMIT();

    float O[16][4];
#pragma unroll
    for (int n = 0; n < 16; n++)
#pragma unroll
        for (int j = 0; j < 4; j++) O[n][j] = 0.f;
    float m0 = -1e30f, m1 = -1e30f, l0 = 0.f, l1 = 0.f;

    for (int kt = kt0; kt < kt1; kt++) {
        CPA_WAIT1();
        __syncthreads();
        const uint32_t sb = smem_u + (uint32_t)((kt - kt0) & 1) * AT_STAGE;
        const int k0 = kt * 64;

        // ---- S = Q K^T ----
        float s[8][4];
#pragma unroll
        for (int n = 0; n < 8; n++)
#pragma unroll
            for (int j = 0; j < 4; j++) s[n][j] = 0.f;

#pragma unroll
        for (int kk = 0; kk < 8; kk++) {
            const uint32_t kc2 = (uint32_t)(kk * 16 + cc8) * 2;
#pragma unroll
            for (int p = 0; p < 4; p++) {
                uint32_t kb[4];
                LDSM4(kb, sb + (uint32_t)((p * 16 + rr) * SQ) * 2 + kc2);
                MMAH(s[2 * p],     qf[kk], kb[0], kb[2]);
                MMAH(s[2 * p + 1], qf[kk], kb[1], kb[3]);
            }
        }

        // ---- causal mask (diagonal tile only) ----
        if (kt == qi) {
            const int row0g = qbase + warp * 16 + gid;
#pragma unroll
            for (int n = 0; n < 8; n++) {
                const int keyg = k0 + n * 8 + tig * 2;
                if (keyg     > row0g)     s[n][0] = -3e30f;
                if (keyg + 1 > row0g)     s[n][1] = -3e30f;
                if (keyg     > row0g + 8) s[n][2] = -3e30f;
                if (keyg + 1 > row0g + 8) s[n][3] = -3e30f;
            }
        }

        // ---- online softmax ----
        float rmax0 = -3e30f, rmax1 = -3e30f;
#pragma unroll
        for (int n = 0; n < 8; n++) {
            rmax0 = fmaxf(rmax0, fmaxf(s[n][0], s[n][1]));
            rmax1 = fmaxf(rmax1, fmaxf(s[n][2], s[n][3]));
        }
        rmax0 = fmaxf(rmax0, __shfl_xor_sync(0xffffffffu, rmax0, 1));
        rmax0 = fmaxf(rmax0, __shfl_xor_sync(0xffffffffu, rmax0, 2));
        rmax1 = fmaxf(rmax1, __shfl_xor_sync(0xffffffffu, rmax1, 1));
        rmax1 = fmaxf(rmax1, __shfl_xor_sync(0xffffffffu, rmax1, 2));

        const float mn0 = fmaxf(m0, rmax0), mn1 = fmaxf(m1, rmax1);
        const float al0 = fexp(m0 - mn0),   al1 = fexp(m1 - mn1);
        m0 = mn0; m1 = mn1;

        float rs0 = 0.f, rs1 = 0.f;
        uint32_t pf[4][4];
#pragma unroll
        for (int n = 0; n < 8; n++) {
            float p0 = fexp(s[n][0] - mn0);
            float p1 = fexp(s[n][1] - mn0);
            float p2 = fexp(s[n][2] - mn1);
            float p3 = fexp(s[n][3] - mn1);
            rs0 += p0 + p1; rs1 += p2 + p3;
            const int kti = n >> 1, base = (n & 1) * 2;
            pf[kti][base]     = hpack(p0, p1);
            pf[kti][base + 1] = hpack(p2, p3);
        }
        rs0 += __shfl_xor_sync(0xffffffffu, rs0, 1);
        rs0 += __shfl_xor_sync(0xffffffffu, rs0, 2);
        rs1 += __shfl_xor_sync(0xffffffffu, rs1, 1);
        rs1 += __shfl_xor_sync(0xffffffffu, rs1, 2);
        l0 = l0 * al0 + rs0;
        l1 = l1 * al1 + rs1;

#pragma unroll
        for (int n = 0; n < 16; n++) {
            O[n][0] *= al0; O[n][1] *= al0;
            O[n][2] *= al1; O[n][3] *= al1;
        }

        // ---- O += P V ----
#pragma unroll
        for (int np = 0; np < 8; np++) {
#pragma unroll
            for (int kk = 0; kk < 4; kk++) {
                uint32_t vb[4];
                LDSM4(vb, sb + 17408u +
                          (uint32_t)((np * 16 + rr) * SX + kk * 16 + cc8) * 2);
                MMAH(O[2 * np],     pf[kk], vb[0], vb[2]);
                MMAH(O[2 * np + 1], pf[kk], vb[1], vb[3]);
            }
        }

        __syncthreads();   // all warps done reading this stage
        if (kt + 2 < kt1) { AT_LOAD(kt + 2, sb); }
        CPA_COMMIT();
    }

    // ---- write unnormalized partials + (m, l) ----
    float* Op = g_Op + (size_t)split * MT * HH;
    const int row0g = tb + qbase + warp * 16 + gid;
#pragma unroll
    for (int nt = 0; nt < 16; nt++) {
        const int h = nt * 8 + tig * 2;
        *(float2*)&Op[(size_t)row0g * HH + h]       = make_float2(O[nt][0], O[nt][1]);
        *(float2*)&Op[(size_t)(row0g + 8) * HH + h] = make_float2(O[nt][2], O[nt][3]);
    }
    if (tig == 0) {
        g_ML[split * MT + row0g]     = make_float2(m0, l0);
        g_ML[split * MT + row0g + 8] = make_float2(m1, l1);
    }
}

// ---------------- split-K combine ----------------
__global__ __launch_bounds__(256)
void combine(float* __restrict__ out) {
    const int token = blockIdx.x * 8 + (threadIdx.x >> 5);
    const int lane = threadIdx.x & 31;
    const float2 ml0 = g_ML[token];
    const float2 ml1 = g_ML[MT + token];
    const float m  = fmaxf(ml0.x, ml1.x);
    const float w0 = __expf(ml0.x - m), w1 = __expf(ml1.x - m);
    const float inv = 1.f / (ml0.y * w0 + ml1.y * w1);
    const float4 o0 = *(const float4*)&g_Op[(size_t)token * HH + lane * 4];
    const float4 o1 = *(const float4*)&g_Op[(size_t)(MT + token) * HH + lane * 4];
    float4 r;
    r.x = (o0.x * w0 + o1.x * w1) * inv;
    r.y = (o0.y * w0 + o1.y * w1) * inv;
    r.z = (o0.z * w0 + o1.z * w1) * inv;
    r.w = (o0.w * w0 + o1.w * w1) * inv;
    *(float4*)&out[(size_t)token * HH + lane * 4] = r;
}

// ---------------- launch ----------------
extern "C" void kernel_launch(void* const* d_in, const int* in_sizes, int n_in,
                              void* d_out, int out_size) {
    const float* x  = (const float*)d_in[0];
    const float* Wq = (const float*)d_in[1];
    const float* Wk = (const float*)d_in[2];
    const float* Wv = (const float*)d_in[3];
    float* out = (float*)d_out;

    conv_w<<<(3 * CC * HH + 255) / 256, 256>>>(Wq, Wk, Wv);

    const int PJ_SMEM = 2 * 128 * SX * (int)sizeof(__half);   // 36864
    cudaFuncSetAttribute(proj_mma, cudaFuncAttributeMaxDynamicSharedMemorySize, PJ_SMEM);
    dim3 pg(MT / 128, 3);
    proj_mma<<<pg, 256, PJ_SMEM>>>(x, 0.08838834764831845f);

    cudaFuncSetAttribute(attn_mma, cudaFuncAttributeMaxDynamicSharedMemorySize, AT_SMEM);
    attn_mma<<<BB * (TT / 64) * 2, 128, AT_SMEM>>>();   // 512 CTAs

    combine<<<MT / 8, 256>>>(out);
}